// round 2
// baseline (speedup 1.0000x reference)
#include <cuda_runtime.h>
#include <math.h>

// Problem constants
#define BATCH 4
#define SEQ   2048
#define DMODEL 1024
#define NHEAD 16
#define DHEAD 64
#define MTOT  (BATCH * SEQ)          // 8192 rows for the projections
#define SCALE 0.125f                 // 1/sqrt(64)

// ---------------------------------------------------------------------------
// Scratch (device globals: allocation inside kernel_launch is forbidden)
// ---------------------------------------------------------------------------
__device__ float g_q[(size_t)MTOT * DMODEL];
__device__ float g_k[(size_t)MTOT * DMODEL];
__device__ float g_v[(size_t)MTOT * DMODEL];
__device__ float g_attn[(size_t)MTOT * DMODEL];

// ---------------------------------------------------------------------------
// SGEMM:  C[m,n] = sum_k A[m,k] * W[n,k]      (i.e.  C = A @ W^T)
// A: [M,K] row-major, W: [N,K] row-major. M,N multiples of 128, K multiple of 16.
// 128x128 block tile, 8x8 per thread, 256 threads.
// ---------------------------------------------------------------------------
#define BM 128
#define BN 128
#define BKT 16

__global__ __launch_bounds__(256)
void gemm_nt_kernel(const float* __restrict__ A, const float* __restrict__ W,
                    float* __restrict__ C, int M, int N, int K)
{
    __shared__ float As[BKT][BM + 4];
    __shared__ float Bs[BKT][BN + 4];

    const int bm = blockIdx.y * BM;
    const int bn = blockIdx.x * BN;
    const int tid = threadIdx.x;
    const int tx = tid & 15;        // 0..15 -> columns (8 each)
    const int ty = tid >> 4;        // 0..15 -> rows    (8 each)

    float acc[8][8];
#pragma unroll
    for (int i = 0; i < 8; i++)
#pragma unroll
        for (int j = 0; j < 8; j++) acc[i][j] = 0.f;

    for (int k0 = 0; k0 < K; k0 += BKT) {
        // Load A tile [BM x BKT] -> As[k][m]; 512 float4 loads over 256 threads
#pragma unroll
        for (int l = 0; l < 2; l++) {
            int idx = tid + l * 256;            // 0..511
            int r = idx >> 2;                   // row within tile 0..127
            int c4 = (idx & 3) * 4;             // 0,4,8,12
            float4 va = *(const float4*)&A[(size_t)(bm + r) * K + k0 + c4];
            As[c4 + 0][r] = va.x; As[c4 + 1][r] = va.y;
            As[c4 + 2][r] = va.z; As[c4 + 3][r] = va.w;
            float4 vb = *(const float4*)&W[(size_t)(bn + r) * K + k0 + c4];
            Bs[c4 + 0][r] = vb.x; Bs[c4 + 1][r] = vb.y;
            Bs[c4 + 2][r] = vb.z; Bs[c4 + 3][r] = vb.w;
        }
        __syncthreads();

#pragma unroll
        for (int kk = 0; kk < BKT; kk++) {
            float a[8], b[8];
            float4 a0 = *(const float4*)&As[kk][ty * 8 + 0];
            float4 a1 = *(const float4*)&As[kk][ty * 8 + 4];
            a[0]=a0.x; a[1]=a0.y; a[2]=a0.z; a[3]=a0.w;
            a[4]=a1.x; a[5]=a1.y; a[6]=a1.z; a[7]=a1.w;
            float4 b0 = *(const float4*)&Bs[kk][tx * 8 + 0];
            float4 b1 = *(const float4*)&Bs[kk][tx * 8 + 4];
            b[0]=b0.x; b[1]=b0.y; b[2]=b0.z; b[3]=b0.w;
            b[4]=b1.x; b[5]=b1.y; b[6]=b1.z; b[7]=b1.w;
#pragma unroll
            for (int i = 0; i < 8; i++)
#pragma unroll
                for (int j = 0; j < 8; j++)
                    acc[i][j] += a[i] * b[j];
        }
        __syncthreads();
    }

#pragma unroll
    for (int i = 0; i < 8; i++) {
#pragma unroll
        for (int j = 0; j < 8; j += 4) {
            float4 v = make_float4(acc[i][j], acc[i][j+1], acc[i][j+2], acc[i][j+3]);
            *(float4*)&C[(size_t)(bm + ty * 8 + i) * N + bn + tx * 8 + j] = v;
        }
    }
}

// ---------------------------------------------------------------------------
// Causal flash attention, fp32, online softmax.
// One thread per query row, 128 query rows per block, 64-key tiles in smem.
// Q/K/V layout: [B, S, D] with head h occupying columns [h*64, h*64+64).
// ---------------------------------------------------------------------------
#define BQ 128
#define BKV 64

__global__ __launch_bounds__(BQ)
void flash_attn_kernel(const float* __restrict__ Q, const float* __restrict__ K,
                       const float* __restrict__ V, float* __restrict__ O)
{
    const int bh = blockIdx.y;
    const int b = bh >> 4;          // /16 heads
    const int h = bh & 15;
    const int q0 = blockIdx.x * BQ;
    const int tid = threadIdx.x;
    const int qi = q0 + tid;

    const float* Qb = Q + ((size_t)b * SEQ) * DMODEL + h * DHEAD;
    const float* Kb = K + ((size_t)b * SEQ) * DMODEL + h * DHEAD;
    const float* Vb = V + ((size_t)b * SEQ) * DMODEL + h * DHEAD;

    __shared__ float Ks[BKV][DHEAD];
    __shared__ float Vs[BKV][DHEAD];

    // Q row into registers, pre-scaled by 1/sqrt(dk)
    float q[DHEAD];
#pragma unroll
    for (int d = 0; d < DHEAD; d += 4) {
        float4 v = *(const float4*)&Qb[(size_t)qi * DMODEL + d];
        q[d+0] = v.x * SCALE; q[d+1] = v.y * SCALE;
        q[d+2] = v.z * SCALE; q[d+3] = v.w * SCALE;
    }

    float acc[DHEAD];
#pragma unroll
    for (int d = 0; d < DHEAD; d++) acc[d] = 0.f;
    float m = -INFINITY;
    float l = 0.f;

    const int kend = q0 + BQ;       // keys beyond the diagonal block are all masked
    for (int k0 = 0; k0 < kend; k0 += BKV) {
        // Cooperative coalesced load of K/V tiles: 64 rows x 64 floats each
#pragma unroll
        for (int li = 0; li < 8; li++) {
            int idx = tid + li * BQ;          // 0..1023 (float4 granularity)
            int r = idx >> 4;                 // 16 float4 per row
            int c = (idx & 15) * 4;
            *(float4*)&Ks[r][c] = *(const float4*)&Kb[(size_t)(k0 + r) * DMODEL + c];
            *(float4*)&Vs[r][c] = *(const float4*)&Vb[(size_t)(k0 + r) * DMODEL + c];
        }
        __syncthreads();

        int jmax = qi - k0 + 1;               // causal: keys with index <= qi
        if (jmax > BKV) jmax = BKV;
        for (int j = 0; j < jmax; j++) {
            float s = 0.f;
#pragma unroll
            for (int d = 0; d < DHEAD; d += 4) {
                float4 kv = *(const float4*)&Ks[j][d];
                s += q[d+0] * kv.x + q[d+1] * kv.y + q[d+2] * kv.z + q[d+3] * kv.w;
            }
            if (s <= m) {
                float p = __expf(s - m);
                l += p;
#pragma unroll
                for (int d = 0; d < DHEAD; d += 4) {
                    float4 vv = *(const float4*)&Vs[j][d];
                    acc[d+0] += p * vv.x; acc[d+1] += p * vv.y;
                    acc[d+2] += p * vv.z; acc[d+3] += p * vv.w;
                }
            } else {
                float alpha = __expf(m - s);   // exp(-inf)=0 handles the first key
                m = s;
                l = l * alpha + 1.f;
#pragma unroll
                for (int d = 0; d < DHEAD; d += 4) {
                    float4 vv = *(const float4*)&Vs[j][d];
                    acc[d+0] = acc[d+0] * alpha + vv.x;
                    acc[d+1] = acc[d+1] * alpha + vv.y;
                    acc[d+2] = acc[d+2] * alpha + vv.z;
                    acc[d+3] = acc[d+3] * alpha + vv.w;
                }
            }
        }
        __syncthreads();
    }

    const float inv = 1.f / l;
    float* Ob = O + ((size_t)b * SEQ + qi) * DMODEL + h * DHEAD;
#pragma unroll
    for (int d = 0; d < DHEAD; d += 4) {
        float4 v = make_float4(acc[d] * inv, acc[d+1] * inv, acc[d+2] * inv, acc[d+3] * inv);
        *(float4*)&Ob[d] = v;
    }
}

// ---------------------------------------------------------------------------
// Launch
// ---------------------------------------------------------------------------
extern "C" void kernel_launch(void* const* d_in, const int* in_sizes, int n_in,
                              void* d_out, int out_size)
{
    const float* x  = (const float*)d_in[0];
    const float* Wq = (const float*)d_in[1];
    const float* Wk = (const float*)d_in[2];
    const float* Wv = (const float*)d_in[3];
    const float* Wo = (const float*)d_in[4];
    float* out = (float*)d_out;

    float *q_ptr, *k_ptr, *v_ptr, *attn_ptr;
    cudaGetSymbolAddress((void**)&q_ptr,    g_q);
    cudaGetSymbolAddress((void**)&k_ptr,    g_k);
    cudaGetSymbolAddress((void**)&v_ptr,    g_v);
    cudaGetSymbolAddress((void**)&attn_ptr, g_attn);

    dim3 ggrid(DMODEL / BN, MTOT / BM);   // (8, 64)
    gemm_nt_kernel<<<ggrid, 256>>>(x, Wq, q_ptr, MTOT, DMODEL, DMODEL);
    gemm_nt_kernel<<<ggrid, 256>>>(x, Wk, k_ptr, MTOT, DMODEL, DMODEL);
    gemm_nt_kernel<<<ggrid, 256>>>(x, Wv, v_ptr, MTOT, DMODEL, DMODEL);

    dim3 agrid(SEQ / BQ, BATCH * NHEAD);  // (16, 64)
    flash_attn_kernel<<<agrid, BQ>>>(q_ptr, k_ptr, v_ptr, attn_ptr);

    gemm_nt_kernel<<<ggrid, 256>>>(attn_ptr, Wo, out, MTOT, DMODEL, DMODEL);
}

// round 4
// speedup vs baseline: 1.4773x; 1.4773x over previous
#include <cuda_runtime.h>
#include <math.h>
#include <stdint.h>

// Problem constants
#define BATCH 4
#define SEQ   2048
#define DMODEL 1024
#define NHEAD 16
#define DHEAD 64
#define MTOT  (BATCH * SEQ)          // 8192 rows for the projections
#define SCALE 0.125f                 // 1/sqrt(64)

// ---------------------------------------------------------------------------
// Scratch (device globals: allocation inside kernel_launch is forbidden)
// ---------------------------------------------------------------------------
__device__ float g_q[(size_t)MTOT * DMODEL];
__device__ float g_k[(size_t)MTOT * DMODEL];
__device__ float g_v[(size_t)MTOT * DMODEL];
__device__ float g_attn[(size_t)MTOT * DMODEL];

// ---------------------------------------------------------------------------
// TF32 tensor-core GEMM:  C[m,n] = sum_k A[m,k] * W[n,k]   (C = A @ W^T)
// A: [M,K] row-major, W: [N,K] row-major.
// Block tile 128x128, K-tile 16, 256 threads = 8 warps in 2(m) x 4(n),
// warp tile 64x32 -> 4x4 grid of m16n8k8 mma per k8 sub-step.
// cp.async double buffering; smem row stride 28 floats (112B):
//   * 16B-aligned rows  -> cp.async 16B legal for every row
//   * (28*r + c) % 32 distinct over r in [0,8) -> conflict-free fragment LDS
// Raw fp32 bits live in smem; cvt.rna.tf32.f32 applied at fragment load
// (round-to-nearest, avoids truncation bias which would accumulate over K).
// ---------------------------------------------------------------------------
#define SROW 28
#define TILE_U32 (128 * SROW)                 // per-matrix per-buffer u32 count
#define GEMM_SMEM_BYTES (4 * TILE_U32 * 4)    // 2 matrices x 2 buffers = 57344 B

__device__ __forceinline__ uint32_t f2tf32(float x) {
    uint32_t u;
    asm("cvt.rna.tf32.f32 %0, %1;" : "=r"(u) : "f"(x));
    return u;
}

__global__ __launch_bounds__(256, 2)
void gemm_tf32_kernel(const float* __restrict__ A, const float* __restrict__ W,
                      float* __restrict__ C, int M, int N, int K)
{
    extern __shared__ uint32_t smem[];
    uint32_t* As = smem;                 // [2][128*SROW]
    uint32_t* Bs = smem + 2 * TILE_U32;  // [2][128*SROW]

    const int bm = blockIdx.y * 128;
    const int bn = blockIdx.x * 128;
    const int tid = threadIdx.x;
    const int lane = tid & 31;
    const int warp = tid >> 5;
    const int wm = (warp >> 2) * 64;     // 0 or 64
    const int wn = (warp & 3) * 32;      // 0,32,64,96

    const uint32_t s_as = (uint32_t)__cvta_generic_to_shared(As);
    const uint32_t s_bs = (uint32_t)__cvta_generic_to_shared(Bs);

    float c[4][4][4];
#pragma unroll
    for (int i = 0; i < 4; i++)
#pragma unroll
        for (int j = 0; j < 4; j++)
#pragma unroll
            for (int r = 0; r < 4; r++) c[i][j][r] = 0.f;

    const int NT = K / 16;

    // async-copy one 128x16 K-tile of A and W into buffer `buf`
    auto cp_tile = [&](int kt, int buf) {
        const int k0 = kt * 16;
        const uint32_t abase = s_as + (uint32_t)(buf * TILE_U32) * 4u;
        const uint32_t bbase = s_bs + (uint32_t)(buf * TILE_U32) * 4u;
#pragma unroll
        for (int l = 0; l < 2; l++) {
            int idx = tid + l * 256;       // 0..511
            int r = idx >> 2;              // 0..127
            int c4 = (idx & 3) * 4;        // 0,4,8,12
            uint32_t da = abase + (uint32_t)(r * SROW + c4) * 4u;
            const float* ga = &A[(size_t)(bm + r) * K + k0 + c4];
            asm volatile("cp.async.ca.shared.global [%0], [%1], 16;\n"
                         :: "r"(da), "l"(ga));
            uint32_t db = bbase + (uint32_t)(r * SROW + c4) * 4u;
            const float* gb = &W[(size_t)(bn + r) * K + k0 + c4];
            asm volatile("cp.async.ca.shared.global [%0], [%1], 16;\n"
                         :: "r"(db), "l"(gb));
        }
        asm volatile("cp.async.commit_group;\n" ::: "memory");
    };

    cp_tile(0, 0);

    for (int kt = 0; kt < NT; kt++) {
        const int buf = kt & 1;
        asm volatile("cp.async.wait_group 0;\n" ::: "memory");
        __syncthreads();
        if (kt + 1 < NT) cp_tile(kt + 1, buf ^ 1);

        const uint32_t* as = As + buf * TILE_U32;
        const uint32_t* bs = Bs + buf * TILE_U32;

#pragma unroll
        for (int s = 0; s < 2; s++) {
            const int kb = s * 8 + (lane & 3);
            uint32_t a[4][4], b[4][2];
#pragma unroll
            for (int i = 0; i < 4; i++) {
                const uint32_t* p = as + (wm + i * 16 + (lane >> 2)) * SROW + kb;
                a[i][0] = f2tf32(__uint_as_float(p[0]));
                a[i][2] = f2tf32(__uint_as_float(p[4]));
                const uint32_t* p8 = p + 8 * SROW;
                a[i][1] = f2tf32(__uint_as_float(p8[0]));
                a[i][3] = f2tf32(__uint_as_float(p8[4]));
            }
#pragma unroll
            for (int j = 0; j < 4; j++) {
                const uint32_t* p = bs + (wn + j * 8 + (lane >> 2)) * SROW + kb;
                b[j][0] = f2tf32(__uint_as_float(p[0]));
                b[j][1] = f2tf32(__uint_as_float(p[4]));
            }
#pragma unroll
            for (int i = 0; i < 4; i++)
#pragma unroll
                for (int j = 0; j < 4; j++) {
                    asm volatile(
                        "mma.sync.aligned.m16n8k8.row.col.f32.tf32.tf32.f32 "
                        "{%0,%1,%2,%3}, {%4,%5,%6,%7}, {%8,%9}, {%0,%1,%2,%3};\n"
                        : "+f"(c[i][j][0]), "+f"(c[i][j][1]),
                          "+f"(c[i][j][2]), "+f"(c[i][j][3])
                        : "r"(a[i][0]), "r"(a[i][1]), "r"(a[i][2]), "r"(a[i][3]),
                          "r"(b[j][0]), "r"(b[j][1]));
                }
        }
        __syncthreads();
    }

    // Epilogue: c0/c1 at (row, 2c..2c+1), c2/c3 at (row+8, same cols)
#pragma unroll
    for (int i = 0; i < 4; i++) {
#pragma unroll
        for (int j = 0; j < 4; j++) {
            int row = bm + wm + i * 16 + (lane >> 2);
            int col = bn + wn + j * 8 + (lane & 3) * 2;
            float2 v01 = make_float2(c[i][j][0], c[i][j][1]);
            float2 v23 = make_float2(c[i][j][2], c[i][j][3]);
            *(float2*)&C[(size_t)row * N + col] = v01;
            *(float2*)&C[(size_t)(row + 8) * N + col] = v23;
        }
    }
}

// ---------------------------------------------------------------------------
// Causal flash attention, fp32, online softmax (unchanged this round).
// One thread per query row, 128 query rows per block, 64-key tiles in smem.
// ---------------------------------------------------------------------------
#define BQ 128
#define BKV 64

__global__ __launch_bounds__(BQ)
void flash_attn_kernel(const float* __restrict__ Q, const float* __restrict__ K,
                       const float* __restrict__ V, float* __restrict__ O)
{
    const int bh = blockIdx.y;
    const int b = bh >> 4;          // /16 heads
    const int h = bh & 15;
    const int q0 = blockIdx.x * BQ;
    const int tid = threadIdx.x;
    const int qi = q0 + tid;

    const float* Qb = Q + ((size_t)b * SEQ) * DMODEL + h * DHEAD;
    const float* Kb = K + ((size_t)b * SEQ) * DMODEL + h * DHEAD;
    const float* Vb = V + ((size_t)b * SEQ) * DMODEL + h * DHEAD;

    __shared__ float Ks[BKV][DHEAD];
    __shared__ float Vs[BKV][DHEAD];

    float q[DHEAD];
#pragma unroll
    for (int d = 0; d < DHEAD; d += 4) {
        float4 v = *(const float4*)&Qb[(size_t)qi * DMODEL + d];
        q[d+0] = v.x * SCALE; q[d+1] = v.y * SCALE;
        q[d+2] = v.z * SCALE; q[d+3] = v.w * SCALE;
    }

    float acc[DHEAD];
#pragma unroll
    for (int d = 0; d < DHEAD; d++) acc[d] = 0.f;
    float m = -INFINITY;
    float l = 0.f;

    const int kend = q0 + BQ;
    for (int k0 = 0; k0 < kend; k0 += BKV) {
#pragma unroll
        for (int li = 0; li < 8; li++) {
            int idx = tid + li * BQ;
            int r = idx >> 4;
            int c = (idx & 15) * 4;
            *(float4*)&Ks[r][c] = *(const float4*)&Kb[(size_t)(k0 + r) * DMODEL + c];
            *(float4*)&Vs[r][c] = *(const float4*)&Vb[(size_t)(k0 + r) * DMODEL + c];
        }
        __syncthreads();

        int jmax = qi - k0 + 1;
        if (jmax > BKV) jmax = BKV;
        for (int j = 0; j < jmax; j++) {
            float s = 0.f;
#pragma unroll
            for (int d = 0; d < DHEAD; d += 4) {
                float4 kv = *(const float4*)&Ks[j][d];
                s += q[d+0] * kv.x + q[d+1] * kv.y + q[d+2] * kv.z + q[d+3] * kv.w;
            }
            if (s <= m) {
                float p = __expf(s - m);
                l += p;
#pragma unroll
                for (int d = 0; d < DHEAD; d += 4) {
                    float4 vv = *(const float4*)&Vs[j][d];
                    acc[d+0] += p * vv.x; acc[d+1] += p * vv.y;
                    acc[d+2] += p * vv.z; acc[d+3] += p * vv.w;
                }
            } else {
                float alpha = __expf(m - s);
                m = s;
                l = l * alpha + 1.f;
#pragma unroll
                for (int d = 0; d < DHEAD; d += 4) {
                    float4 vv = *(const float4*)&Vs[j][d];
                    acc[d+0] = acc[d+0] * alpha + vv.x;
                    acc[d+1] = acc[d+1] * alpha + vv.y;
                    acc[d+2] = acc[d+2] * alpha + vv.z;
                    acc[d+3] = acc[d+3] * alpha + vv.w;
                }
            }
        }
        __syncthreads();
    }

    const float inv = 1.f / l;
    float* Ob = O + ((size_t)b * SEQ + qi) * DMODEL + h * DHEAD;
#pragma unroll
    for (int d = 0; d < DHEAD; d += 4) {
        float4 v = make_float4(acc[d] * inv, acc[d+1] * inv, acc[d+2] * inv, acc[d+3] * inv);
        *(float4*)&Ob[d] = v;
    }
}

// ---------------------------------------------------------------------------
// Launch
// ---------------------------------------------------------------------------
extern "C" void kernel_launch(void* const* d_in, const int* in_sizes, int n_in,
                              void* d_out, int out_size)
{
    const float* x  = (const float*)d_in[0];
    const float* Wq = (const float*)d_in[1];
    const float* Wk = (const float*)d_in[2];
    const float* Wv = (const float*)d_in[3];
    const float* Wo = (const float*)d_in[4];
    float* out = (float*)d_out;

    float *q_ptr, *k_ptr, *v_ptr, *attn_ptr;
    cudaGetSymbolAddress((void**)&q_ptr,    g_q);
    cudaGetSymbolAddress((void**)&k_ptr,    g_k);
    cudaGetSymbolAddress((void**)&v_ptr,    g_v);
    cudaGetSymbolAddress((void**)&attn_ptr, g_attn);

    static int smem_set = 0;
    if (!smem_set) {
        cudaFuncSetAttribute(gemm_tf32_kernel,
                             cudaFuncAttributeMaxDynamicSharedMemorySize,
                             GEMM_SMEM_BYTES);
        smem_set = 1;
    }

    dim3 ggrid(DMODEL / 128, MTOT / 128);   // (8, 64)
    gemm_tf32_kernel<<<ggrid, 256, GEMM_SMEM_BYTES>>>(x, Wq, q_ptr, MTOT, DMODEL, DMODEL);
    gemm_tf32_kernel<<<ggrid, 256, GEMM_SMEM_BYTES>>>(x, Wk, k_ptr, MTOT, DMODEL, DMODEL);
    gemm_tf32_kernel<<<ggrid, 256, GEMM_SMEM_BYTES>>>(x, Wv, v_ptr, MTOT, DMODEL, DMODEL);

    dim3 agrid(SEQ / BQ, BATCH * NHEAD);    // (16, 64)
    flash_attn_kernel<<<agrid, BQ>>>(q_ptr, k_ptr, v_ptr, attn_ptr);

    gemm_tf32_kernel<<<ggrid, 256, GEMM_SMEM_BYTES>>>(attn_ptr, Wo, out, MTOT, DMODEL, DMODEL);
}

// round 5
// speedup vs baseline: 3.1583x; 2.1378x over previous
#include <cuda_runtime.h>
#include <math.h>
#include <stdint.h>

// Problem constants
#define BATCH 4
#define SEQ   2048
#define DMODEL 1024
#define NHEAD 16
#define DHEAD 64
#define MTOT  (BATCH * SEQ)
#define SCALE 0.125f                 // 1/sqrt(64)

// ---------------------------------------------------------------------------
// Scratch
// ---------------------------------------------------------------------------
__device__ float g_q[(size_t)MTOT * DMODEL];
__device__ float g_k[(size_t)MTOT * DMODEL];
__device__ float g_v[(size_t)MTOT * DMODEL];
__device__ float g_attn[(size_t)MTOT * DMODEL];

__device__ __forceinline__ uint32_t f2tf32(float x) {
    uint32_t u;
    asm("cvt.rna.tf32.f32 %0, %1;" : "=r"(u) : "f"(x));
    return u;
}

__device__ __forceinline__ void mma_tf32(float c[4], const uint32_t a[4],
                                         uint32_t b0, uint32_t b1) {
    asm volatile(
        "mma.sync.aligned.m16n8k8.row.col.f32.tf32.tf32.f32 "
        "{%0,%1,%2,%3}, {%4,%5,%6,%7}, {%8,%9}, {%0,%1,%2,%3};\n"
        : "+f"(c[0]), "+f"(c[1]), "+f"(c[2]), "+f"(c[3])
        : "r"(a[0]), "r"(a[1]), "r"(a[2]), "r"(a[3]), "r"(b0), "r"(b1));
}

// ---------------------------------------------------------------------------
// TF32 tensor-core GEMM (unchanged from round 4):
// C[m,n] = sum_k A[m,k]*W[n,k]; 128x128 tile, cp.async double buffer.
// ---------------------------------------------------------------------------
#define SROW 28
#define TILE_U32 (128 * SROW)
#define GEMM_SMEM_BYTES (4 * TILE_U32 * 4)

__global__ __launch_bounds__(256, 2)
void gemm_tf32_kernel(const float* __restrict__ A, const float* __restrict__ W,
                      float* __restrict__ C, int M, int N, int K)
{
    extern __shared__ uint32_t smem[];
    uint32_t* As = smem;
    uint32_t* Bs = smem + 2 * TILE_U32;

    const int bm = blockIdx.y * 128;
    const int bn = blockIdx.x * 128;
    const int tid = threadIdx.x;
    const int lane = tid & 31;
    const int warp = tid >> 5;
    const int wm = (warp >> 2) * 64;
    const int wn = (warp & 3) * 32;

    const uint32_t s_as = (uint32_t)__cvta_generic_to_shared(As);
    const uint32_t s_bs = (uint32_t)__cvta_generic_to_shared(Bs);

    float c[4][4][4];
#pragma unroll
    for (int i = 0; i < 4; i++)
#pragma unroll
        for (int j = 0; j < 4; j++)
#pragma unroll
            for (int r = 0; r < 4; r++) c[i][j][r] = 0.f;

    const int NT = K / 16;

    auto cp_tile = [&](int kt, int buf) {
        const int k0 = kt * 16;
        const uint32_t abase = s_as + (uint32_t)(buf * TILE_U32) * 4u;
        const uint32_t bbase = s_bs + (uint32_t)(buf * TILE_U32) * 4u;
#pragma unroll
        for (int l = 0; l < 2; l++) {
            int idx = tid + l * 256;
            int r = idx >> 2;
            int c4 = (idx & 3) * 4;
            uint32_t da = abase + (uint32_t)(r * SROW + c4) * 4u;
            const float* ga = &A[(size_t)(bm + r) * K + k0 + c4];
            asm volatile("cp.async.ca.shared.global [%0], [%1], 16;\n"
                         :: "r"(da), "l"(ga));
            uint32_t db = bbase + (uint32_t)(r * SROW + c4) * 4u;
            const float* gb = &W[(size_t)(bn + r) * K + k0 + c4];
            asm volatile("cp.async.ca.shared.global [%0], [%1], 16;\n"
                         :: "r"(db), "l"(gb));
        }
        asm volatile("cp.async.commit_group;\n" ::: "memory");
    };

    cp_tile(0, 0);

    for (int kt = 0; kt < NT; kt++) {
        const int buf = kt & 1;
        asm volatile("cp.async.wait_group 0;\n" ::: "memory");
        __syncthreads();
        if (kt + 1 < NT) cp_tile(kt + 1, buf ^ 1);

        const uint32_t* as = As + buf * TILE_U32;
        const uint32_t* bs = Bs + buf * TILE_U32;

#pragma unroll
        for (int s = 0; s < 2; s++) {
            const int kb = s * 8 + (lane & 3);
            uint32_t a[4][4], b[4][2];
#pragma unroll
            for (int i = 0; i < 4; i++) {
                const uint32_t* p = as + (wm + i * 16 + (lane >> 2)) * SROW + kb;
                a[i][0] = f2tf32(__uint_as_float(p[0]));
                a[i][2] = f2tf32(__uint_as_float(p[4]));
                const uint32_t* p8 = p + 8 * SROW;
                a[i][1] = f2tf32(__uint_as_float(p8[0]));
                a[i][3] = f2tf32(__uint_as_float(p8[4]));
            }
#pragma unroll
            for (int j = 0; j < 4; j++) {
                const uint32_t* p = bs + (wn + j * 8 + (lane >> 2)) * SROW + kb;
                b[j][0] = f2tf32(__uint_as_float(p[0]));
                b[j][1] = f2tf32(__uint_as_float(p[4]));
            }
#pragma unroll
            for (int i = 0; i < 4; i++)
#pragma unroll
                for (int j = 0; j < 4; j++)
                    mma_tf32(c[i][j], a[i], b[j][0], b[j][1]);
        }
        __syncthreads();
    }

#pragma unroll
    for (int i = 0; i < 4; i++) {
#pragma unroll
        for (int j = 0; j < 4; j++) {
            int row = bm + wm + i * 16 + (lane >> 2);
            int col = bn + wn + j * 8 + (lane & 3) * 2;
            *(float2*)&C[(size_t)row * N + col] = make_float2(c[i][j][0], c[i][j][1]);
            *(float2*)&C[(size_t)(row + 8) * N + col] = make_float2(c[i][j][2], c[i][j][3]);
        }
    }
}

// ---------------------------------------------------------------------------
// Tensor-core causal flash attention (tf32 mma, online softmax on fragments).
// Block: 128 threads = 4 warps. Q tile 64 (warp = 16 rows), KV tile 64.
// K smem stride 68 floats -> (4r+q) distinct mod 32 on fragment LDS.
// V smem stride 72 floats -> (8q+r) distinct mod 32 on fragment LDS.
// P fragments for P@V assembled via intra-warp shuffles (no smem trip).
// ---------------------------------------------------------------------------
#define KSTR 68
#define VSTR 72

__global__ __launch_bounds__(128)
void flash_mma_kernel(const float* __restrict__ Q, const float* __restrict__ K,
                      const float* __restrict__ V, float* __restrict__ O)
{
    __shared__ float Ks[64][KSTR];
    __shared__ float Vs[64][VSTR];

    const int bh = blockIdx.y;
    const int b = bh >> 4;
    const int h = bh & 15;
    const int qb = blockIdx.x;
    const int q0 = qb * 64;
    const int tid = threadIdx.x;
    const int lane = tid & 31;
    const int warp = tid >> 5;
    const int wm = warp * 16;
    const int r = lane >> 2;          // fragment row within 8
    const int qq = lane & 3;          // fragment k/col index

    const float* Qb = Q + ((size_t)b * SEQ) * DMODEL + h * DHEAD;
    const float* Kb = K + ((size_t)b * SEQ) * DMODEL + h * DHEAD;
    const float* Vb = V + ((size_t)b * SEQ) * DMODEL + h * DHEAD;

    // ---- Stage Q tile through Ks, extract A fragments (pre-scaled) ----
#pragma unroll
    for (int i = 0; i < 8; i++) {
        int idx = tid + i * 128;
        int rr = idx >> 4;
        int cc = (idx & 15) * 4;
        *(float4*)&Ks[rr][cc] = *(const float4*)&Qb[(size_t)(q0 + rr) * DMODEL + cc];
    }
    __syncthreads();

    uint32_t qf[8][4];
#pragma unroll
    for (int kk = 0; kk < 8; kk++) {
        qf[kk][0] = f2tf32(Ks[wm + r][kk * 8 + qq] * SCALE);
        qf[kk][1] = f2tf32(Ks[wm + r + 8][kk * 8 + qq] * SCALE);
        qf[kk][2] = f2tf32(Ks[wm + r][kk * 8 + qq + 4] * SCALE);
        qf[kk][3] = f2tf32(Ks[wm + r + 8][kk * 8 + qq + 4] * SCALE);
    }
    __syncthreads();

    float o[8][4];
#pragma unroll
    for (int j = 0; j < 8; j++)
#pragma unroll
        for (int x = 0; x < 4; x++) o[j][x] = 0.f;
    float m0 = -INFINITY, m1 = -INFINITY;
    float l0 = 0.f, l1 = 0.f;

    const int base = lane & 28;
    const int sl0 = base + (qq >> 1);
    const int sl1 = sl0 + 2;
    const bool odd = (qq & 1);

    for (int t = 0; t <= qb; t++) {
        const int k0 = t * 64;
        // ---- cooperative K/V tile load ----
#pragma unroll
        for (int i = 0; i < 8; i++) {
            int idx = tid + i * 128;
            int rr = idx >> 4;
            int cc = (idx & 15) * 4;
            *(float4*)&Ks[rr][cc] = *(const float4*)&Kb[(size_t)(k0 + rr) * DMODEL + cc];
            *(float4*)&Vs[rr][cc] = *(const float4*)&Vb[(size_t)(k0 + rr) * DMODEL + cc];
        }
        __syncthreads();

        // ---- S = Q @ K^T ----
        float cf[8][4];
#pragma unroll
        for (int j = 0; j < 8; j++) {
#pragma unroll
            for (int x = 0; x < 4; x++) cf[j][x] = 0.f;
#pragma unroll
            for (int kk = 0; kk < 8; kk++) {
                uint32_t b0 = f2tf32(Ks[j * 8 + r][kk * 8 + qq]);
                uint32_t b1 = f2tf32(Ks[j * 8 + r][kk * 8 + qq + 4]);
                mma_tf32(cf[j], qf[kk], b0, b1);
            }
        }

        // ---- causal mask on diagonal tile (block-local indices) ----
        if (t == qb) {
            const int row0 = wm + r;
            const int row1 = wm + r + 8;
#pragma unroll
            for (int j = 0; j < 8; j++) {
                int kc = j * 8 + 2 * qq;
                if (kc > row0)     cf[j][0] = -INFINITY;
                if (kc + 1 > row0) cf[j][1] = -INFINITY;
                if (kc > row1)     cf[j][2] = -INFINITY;
                if (kc + 1 > row1) cf[j][3] = -INFINITY;
            }
        }

        // ---- online softmax on fragments ----
        float t0 = -INFINITY, t1 = -INFINITY;
#pragma unroll
        for (int j = 0; j < 8; j++) {
            t0 = fmaxf(t0, fmaxf(cf[j][0], cf[j][1]));
            t1 = fmaxf(t1, fmaxf(cf[j][2], cf[j][3]));
        }
        t0 = fmaxf(t0, __shfl_xor_sync(0xffffffffu, t0, 1));
        t0 = fmaxf(t0, __shfl_xor_sync(0xffffffffu, t0, 2));
        t1 = fmaxf(t1, __shfl_xor_sync(0xffffffffu, t1, 1));
        t1 = fmaxf(t1, __shfl_xor_sync(0xffffffffu, t1, 2));

        float nm0 = fmaxf(m0, t0);
        float nm1 = fmaxf(m1, t1);
        float alpha0 = __expf(m0 - nm0);
        float alpha1 = __expf(m1 - nm1);
        m0 = nm0; m1 = nm1;

        float rs0 = 0.f, rs1 = 0.f;
#pragma unroll
        for (int j = 0; j < 8; j++) {
            cf[j][0] = __expf(cf[j][0] - m0); rs0 += cf[j][0];
            cf[j][1] = __expf(cf[j][1] - m0); rs0 += cf[j][1];
            cf[j][2] = __expf(cf[j][2] - m1); rs1 += cf[j][2];
            cf[j][3] = __expf(cf[j][3] - m1); rs1 += cf[j][3];
        }
        rs0 += __shfl_xor_sync(0xffffffffu, rs0, 1);
        rs0 += __shfl_xor_sync(0xffffffffu, rs0, 2);
        rs1 += __shfl_xor_sync(0xffffffffu, rs1, 1);
        rs1 += __shfl_xor_sync(0xffffffffu, rs1, 2);
        l0 = l0 * alpha0 + rs0;
        l1 = l1 * alpha1 + rs1;

#pragma unroll
        for (int j = 0; j < 8; j++) {
            o[j][0] *= alpha0; o[j][1] *= alpha0;
            o[j][2] *= alpha1; o[j][3] *= alpha1;
        }

        // ---- O += P @ V : assemble P A-fragments via shuffles ----
#pragma unroll
        for (int kk = 0; kk < 8; kk++) {
            float v00 = __shfl_sync(0xffffffffu, cf[kk][0], sl0);
            float v01 = __shfl_sync(0xffffffffu, cf[kk][1], sl0);
            float v20 = __shfl_sync(0xffffffffu, cf[kk][0], sl1);
            float v21 = __shfl_sync(0xffffffffu, cf[kk][1], sl1);
            float v10 = __shfl_sync(0xffffffffu, cf[kk][2], sl0);
            float v11 = __shfl_sync(0xffffffffu, cf[kk][3], sl0);
            float v30 = __shfl_sync(0xffffffffu, cf[kk][2], sl1);
            float v31 = __shfl_sync(0xffffffffu, cf[kk][3], sl1);
            uint32_t pa[4];
            pa[0] = f2tf32(odd ? v01 : v00);
            pa[1] = f2tf32(odd ? v11 : v10);
            pa[2] = f2tf32(odd ? v21 : v20);
            pa[3] = f2tf32(odd ? v31 : v30);
#pragma unroll
            for (int j2 = 0; j2 < 8; j2++) {
                uint32_t b0 = f2tf32(Vs[kk * 8 + qq][j2 * 8 + r]);
                uint32_t b1 = f2tf32(Vs[kk * 8 + qq + 4][j2 * 8 + r]);
                mma_tf32(o[j2], pa, b0, b1);
            }
        }
        __syncthreads();
    }

    // ---- epilogue: normalize and store ----
    const float inv0 = 1.f / l0;
    const float inv1 = 1.f / l1;
    float* Ob = O + ((size_t)b * SEQ) * DMODEL + h * DHEAD;
    const int row0 = q0 + wm + r;
#pragma unroll
    for (int j2 = 0; j2 < 8; j2++) {
        int col = j2 * 8 + 2 * qq;
        *(float2*)&Ob[(size_t)row0 * DMODEL + col] =
            make_float2(o[j2][0] * inv0, o[j2][1] * inv0);
        *(float2*)&Ob[(size_t)(row0 + 8) * DMODEL + col] =
            make_float2(o[j2][2] * inv1, o[j2][3] * inv1);
    }
}

// ---------------------------------------------------------------------------
// Launch
// ---------------------------------------------------------------------------
extern "C" void kernel_launch(void* const* d_in, const int* in_sizes, int n_in,
                              void* d_out, int out_size)
{
    const float* x  = (const float*)d_in[0];
    const float* Wq = (const float*)d_in[1];
    const float* Wk = (const float*)d_in[2];
    const float* Wv = (const float*)d_in[3];
    const float* Wo = (const float*)d_in[4];
    float* out = (float*)d_out;

    float *q_ptr, *k_ptr, *v_ptr, *attn_ptr;
    cudaGetSymbolAddress((void**)&q_ptr,    g_q);
    cudaGetSymbolAddress((void**)&k_ptr,    g_k);
    cudaGetSymbolAddress((void**)&v_ptr,    g_v);
    cudaGetSymbolAddress((void**)&attn_ptr, g_attn);

    static int smem_set = 0;
    if (!smem_set) {
        cudaFuncSetAttribute(gemm_tf32_kernel,
                             cudaFuncAttributeMaxDynamicSharedMemorySize,
                             GEMM_SMEM_BYTES);
        smem_set = 1;
    }

    dim3 ggrid(DMODEL / 128, MTOT / 128);   // (8, 64)
    gemm_tf32_kernel<<<ggrid, 256, GEMM_SMEM_BYTES>>>(x, Wq, q_ptr, MTOT, DMODEL, DMODEL);
    gemm_tf32_kernel<<<ggrid, 256, GEMM_SMEM_BYTES>>>(x, Wk, k_ptr, MTOT, DMODEL, DMODEL);
    gemm_tf32_kernel<<<ggrid, 256, GEMM_SMEM_BYTES>>>(x, Wv, v_ptr, MTOT, DMODEL, DMODEL);

    dim3 agrid(SEQ / 64, BATCH * NHEAD);    // (32, 64)
    flash_mma_kernel<<<agrid, 128>>>(q_ptr, k_ptr, v_ptr, attn_ptr);

    gemm_tf32_kernel<<<ggrid, 256, GEMM_SMEM_BYTES>>>(attn_ptr, Wo, out, MTOT, DMODEL, DMODEL);
}

// round 6
// speedup vs baseline: 3.5652x; 1.1288x over previous
#include <cuda_runtime.h>
#include <math.h>
#include <stdint.h>

// Problem constants
#define BATCH 4
#define SEQ   2048
#define DMODEL 1024
#define NHEAD 16
#define DHEAD 64
#define MTOT  (BATCH * SEQ)
#define SCALE 0.125f                 // 1/sqrt(64)
#define WELEM (DMODEL * DMODEL)      // 1M elements per weight

// ---------------------------------------------------------------------------
// Scratch (device globals)
// ---------------------------------------------------------------------------
__device__ float    g_q[(size_t)MTOT * DMODEL];
__device__ float    g_k[(size_t)MTOT * DMODEL];
__device__ float    g_v[(size_t)MTOT * DMODEL];
__device__ float    g_attn[(size_t)MTOT * DMODEL];
__device__ uint32_t g_xt[(size_t)MTOT * DMODEL];    // x, pre-converted tf32 bits
__device__ uint32_t g_at[(size_t)MTOT * DMODEL];    // attn, pre-converted
__device__ uint32_t g_wt[(size_t)4 * WELEM];        // Wq|Wk|Wv|Wo, pre-converted

__device__ __forceinline__ uint32_t f2tf32(float x) {
    uint32_t u;
    asm("cvt.rna.tf32.f32 %0, %1;" : "=r"(u) : "f"(x));
    return u;
}

__device__ __forceinline__ void mma_tf32(float c[4], const uint32_t a[4],
                                         uint32_t b0, uint32_t b1) {
    asm volatile(
        "mma.sync.aligned.m16n8k8.row.col.f32.tf32.tf32.f32 "
        "{%0,%1,%2,%3}, {%4,%5,%6,%7}, {%8,%9}, {%0,%1,%2,%3};\n"
        : "+f"(c[0]), "+f"(c[1]), "+f"(c[2]), "+f"(c[3])
        : "r"(a[0]), "r"(a[1]), "r"(a[2]), "r"(a[3]), "r"(b0), "r"(b1));
}

// ---------------------------------------------------------------------------
// fp32 -> tf32-bits conversion kernels (bandwidth-bound, trivial)
// ---------------------------------------------------------------------------
__global__ __launch_bounds__(256)
void conv_tf32_kernel(const float* __restrict__ in, uint32_t* __restrict__ out)
{
    // one float4 per thread; grid sized exactly
    size_t i = ((size_t)blockIdx.x * 256 + threadIdx.x) * 4;
    float4 v = *(const float4*)&in[i];
    uint4 u = make_uint4(f2tf32(v.x), f2tf32(v.y), f2tf32(v.z), f2tf32(v.w));
    *(uint4*)&out[i] = u;
}

__global__ __launch_bounds__(256)
void conv_w_kernel(const float* __restrict__ w0, const float* __restrict__ w1,
                   const float* __restrict__ w2, const float* __restrict__ w3)
{
    const float* src = (blockIdx.z == 0) ? w0 : (blockIdx.z == 1) ? w1
                     : (blockIdx.z == 2) ? w2 : w3;
    size_t i = ((size_t)blockIdx.x * 256 + threadIdx.x) * 4;
    float4 v = *(const float4*)&src[i];
    uint4 u = make_uint4(f2tf32(v.x), f2tf32(v.y), f2tf32(v.z), f2tf32(v.w));
    *(uint4*)&g_wt[(size_t)blockIdx.z * WELEM + i] = u;
}

// ---------------------------------------------------------------------------
// TF32 GEMM on pre-converted inputs:  C = A @ W^T
// A,W hold tf32 bit patterns. 128x128 tile, k-tile 16, cp.async double buffer,
// 256 threads = 8 warps (2m x 4n), warp tile 64x32. Hot loop: LDS + MMA only.
// ---------------------------------------------------------------------------
#define SROW 28
#define TILE_U32 (128 * SROW)
#define GEMM_SMEM_BYTES (4 * TILE_U32 * 4)

__device__ __forceinline__
void gemm_body(uint32_t* smem, const uint32_t* __restrict__ A,
               const uint32_t* __restrict__ W, float* __restrict__ C,
               int M, int N, int K, int bm, int bn)
{
    uint32_t* As = smem;
    uint32_t* Bs = smem + 2 * TILE_U32;

    const int tid = threadIdx.x;
    const int lane = tid & 31;
    const int warp = tid >> 5;
    const int wm = (warp >> 2) * 64;
    const int wn = (warp & 3) * 32;

    const uint32_t s_as = (uint32_t)__cvta_generic_to_shared(As);
    const uint32_t s_bs = (uint32_t)__cvta_generic_to_shared(Bs);

    float c[4][4][4];
#pragma unroll
    for (int i = 0; i < 4; i++)
#pragma unroll
        for (int j = 0; j < 4; j++)
#pragma unroll
            for (int r = 0; r < 4; r++) c[i][j][r] = 0.f;

    const int NT = K / 16;

    auto cp_tile = [&](int kt, int buf) {
        const int k0 = kt * 16;
        const uint32_t abase = s_as + (uint32_t)(buf * TILE_U32) * 4u;
        const uint32_t bbase = s_bs + (uint32_t)(buf * TILE_U32) * 4u;
#pragma unroll
        for (int l = 0; l < 2; l++) {
            int idx = tid + l * 256;
            int r = idx >> 2;
            int c4 = (idx & 3) * 4;
            uint32_t da = abase + (uint32_t)(r * SROW + c4) * 4u;
            const uint32_t* ga = &A[(size_t)(bm + r) * K + k0 + c4];
            asm volatile("cp.async.ca.shared.global [%0], [%1], 16;\n"
                         :: "r"(da), "l"(ga));
            uint32_t db = bbase + (uint32_t)(r * SROW + c4) * 4u;
            const uint32_t* gb = &W[(size_t)(bn + r) * K + k0 + c4];
            asm volatile("cp.async.ca.shared.global [%0], [%1], 16;\n"
                         :: "r"(db), "l"(gb));
        }
        asm volatile("cp.async.commit_group;\n" ::: "memory");
    };

    cp_tile(0, 0);

    for (int kt = 0; kt < NT; kt++) {
        const int buf = kt & 1;
        asm volatile("cp.async.wait_group 0;\n" ::: "memory");
        __syncthreads();
        if (kt + 1 < NT) cp_tile(kt + 1, buf ^ 1);

        const uint32_t* as = As + buf * TILE_U32;
        const uint32_t* bs = Bs + buf * TILE_U32;

#pragma unroll
        for (int s = 0; s < 2; s++) {
            const int kb = s * 8 + (lane & 3);
            uint32_t a[4][4], b[4][2];
#pragma unroll
            for (int i = 0; i < 4; i++) {
                const uint32_t* p = as + (wm + i * 16 + (lane >> 2)) * SROW + kb;
                a[i][0] = p[0];
                a[i][2] = p[4];
                const uint32_t* p8 = p + 8 * SROW;
                a[i][1] = p8[0];
                a[i][3] = p8[4];
            }
#pragma unroll
            for (int j = 0; j < 4; j++) {
                const uint32_t* p = bs + (wn + j * 8 + (lane >> 2)) * SROW + kb;
                b[j][0] = p[0];
                b[j][1] = p[4];
            }
#pragma unroll
            for (int i = 0; i < 4; i++)
#pragma unroll
                for (int j = 0; j < 4; j++)
                    mma_tf32(c[i][j], a[i], b[j][0], b[j][1]);
        }
        __syncthreads();
    }

#pragma unroll
    for (int i = 0; i < 4; i++) {
#pragma unroll
        for (int j = 0; j < 4; j++) {
            int row = bm + wm + i * 16 + (lane >> 2);
            int col = bn + wn + j * 8 + (lane & 3) * 2;
            *(float2*)&C[(size_t)row * N + col] = make_float2(c[i][j][0], c[i][j][1]);
            *(float2*)&C[(size_t)(row + 8) * N + col] = make_float2(c[i][j][2], c[i][j][3]);
        }
    }
}

// Fused Q/K/V projection: blockIdx.z selects weight slice and output buffer.
__global__ __launch_bounds__(256, 2)
void gemm_qkv_kernel()
{
    extern __shared__ uint32_t smem[];
    const int z = blockIdx.z;
    float* C = (z == 0) ? g_q : (z == 1) ? g_k : g_v;
    gemm_body(smem, g_xt, g_wt + (size_t)z * WELEM, C,
              MTOT, DMODEL, DMODEL, blockIdx.y * 128, blockIdx.x * 128);
}

// Output projection: attn(tf32) @ Wo^T -> out
__global__ __launch_bounds__(256, 2)
void gemm_out_kernel(float* __restrict__ out)
{
    extern __shared__ uint32_t smem[];
    gemm_body(smem, g_at, g_wt + (size_t)3 * WELEM, out,
              MTOT, DMODEL, DMODEL, blockIdx.y * 128, blockIdx.x * 128);
}

// ---------------------------------------------------------------------------
// Tensor-core causal flash attention. K/V converted to tf32 ONCE at tile load;
// hot loops are LDS+MMA (+softmax). Heavy blocks launched first (reversed qb).
// ---------------------------------------------------------------------------
#define KSTR 68
#define VSTR 72

__global__ __launch_bounds__(128)
void flash_mma_kernel(const float* __restrict__ Q, const float* __restrict__ K,
                      const float* __restrict__ V, float* __restrict__ O)
{
    __shared__ uint32_t Ks[64][KSTR];
    __shared__ uint32_t Vs[64][VSTR];

    const int bh = blockIdx.y;
    const int b = bh >> 4;
    const int h = bh & 15;
    const int qb = gridDim.x - 1 - blockIdx.x;   // heavy blocks first
    const int q0 = qb * 64;
    const int tid = threadIdx.x;
    const int lane = tid & 31;
    const int warp = tid >> 5;
    const int wm = warp * 16;
    const int r = lane >> 2;
    const int qq = lane & 3;

    const float* Qb = Q + ((size_t)b * SEQ) * DMODEL + h * DHEAD;
    const float* Kb = K + ((size_t)b * SEQ) * DMODEL + h * DHEAD;
    const float* Vb = V + ((size_t)b * SEQ) * DMODEL + h * DHEAD;

    // ---- Stage Q tile (raw bits) through Ks, extract A fragments ----
#pragma unroll
    for (int i = 0; i < 8; i++) {
        int idx = tid + i * 128;
        int rr = idx >> 4;
        int cc = (idx & 15) * 4;
        *(float4*)&Ks[rr][cc] = *(const float4*)&Qb[(size_t)(q0 + rr) * DMODEL + cc];
    }
    __syncthreads();

    uint32_t qf[8][4];
#pragma unroll
    for (int kk = 0; kk < 8; kk++) {
        qf[kk][0] = f2tf32(__uint_as_float(Ks[wm + r][kk * 8 + qq]) * SCALE);
        qf[kk][1] = f2tf32(__uint_as_float(Ks[wm + r + 8][kk * 8 + qq]) * SCALE);
        qf[kk][2] = f2tf32(__uint_as_float(Ks[wm + r][kk * 8 + qq + 4]) * SCALE);
        qf[kk][3] = f2tf32(__uint_as_float(Ks[wm + r + 8][kk * 8 + qq + 4]) * SCALE);
    }
    __syncthreads();

    float o[8][4];
#pragma unroll
    for (int j = 0; j < 8; j++)
#pragma unroll
        for (int x = 0; x < 4; x++) o[j][x] = 0.f;
    float m0 = -INFINITY, m1 = -INFINITY;
    float l0 = 0.f, l1 = 0.f;

    const int base = lane & 28;
    const int sl0 = base + (qq >> 1);
    const int sl1 = sl0 + 2;
    const bool odd = (qq & 1);

    for (int t = 0; t <= qb; t++) {
        const int k0 = t * 64;
        // ---- cooperative K/V tile load, tf32 conversion at load ----
#pragma unroll
        for (int i = 0; i < 8; i++) {
            int idx = tid + i * 128;
            int rr = idx >> 4;
            int cc = (idx & 15) * 4;
            float4 kv = *(const float4*)&Kb[(size_t)(k0 + rr) * DMODEL + cc];
            float4 vv = *(const float4*)&Vb[(size_t)(k0 + rr) * DMODEL + cc];
            *(uint4*)&Ks[rr][cc] =
                make_uint4(f2tf32(kv.x), f2tf32(kv.y), f2tf32(kv.z), f2tf32(kv.w));
            *(uint4*)&Vs[rr][cc] =
                make_uint4(f2tf32(vv.x), f2tf32(vv.y), f2tf32(vv.z), f2tf32(vv.w));
        }
        __syncthreads();

        // ---- S = Q @ K^T (pure LDS + MMA) ----
        float cf[8][4];
#pragma unroll
        for (int j = 0; j < 8; j++) {
#pragma unroll
            for (int x = 0; x < 4; x++) cf[j][x] = 0.f;
#pragma unroll
            for (int kk = 0; kk < 8; kk++) {
                uint32_t b0 = Ks[j * 8 + r][kk * 8 + qq];
                uint32_t b1 = Ks[j * 8 + r][kk * 8 + qq + 4];
                mma_tf32(cf[j], qf[kk], b0, b1);
            }
        }

        // ---- causal mask on diagonal tile ----
        if (t == qb) {
            const int row0 = wm + r;
            const int row1 = wm + r + 8;
#pragma unroll
            for (int j = 0; j < 8; j++) {
                int kc = j * 8 + 2 * qq;
                if (kc > row0)     cf[j][0] = -INFINITY;
                if (kc + 1 > row0) cf[j][1] = -INFINITY;
                if (kc > row1)     cf[j][2] = -INFINITY;
                if (kc + 1 > row1) cf[j][3] = -INFINITY;
            }
        }

        // ---- online softmax on fragments ----
        float t0 = -INFINITY, t1 = -INFINITY;
#pragma unroll
        for (int j = 0; j < 8; j++) {
            t0 = fmaxf(t0, fmaxf(cf[j][0], cf[j][1]));
            t1 = fmaxf(t1, fmaxf(cf[j][2], cf[j][3]));
        }
        t0 = fmaxf(t0, __shfl_xor_sync(0xffffffffu, t0, 1));
        t0 = fmaxf(t0, __shfl_xor_sync(0xffffffffu, t0, 2));
        t1 = fmaxf(t1, __shfl_xor_sync(0xffffffffu, t1, 1));
        t1 = fmaxf(t1, __shfl_xor_sync(0xffffffffu, t1, 2));

        float nm0 = fmaxf(m0, t0);
        float nm1 = fmaxf(m1, t1);
        float alpha0 = __expf(m0 - nm0);
        float alpha1 = __expf(m1 - nm1);
        m0 = nm0; m1 = nm1;

        float rs0 = 0.f, rs1 = 0.f;
#pragma unroll
        for (int j = 0; j < 8; j++) {
            cf[j][0] = __expf(cf[j][0] - m0); rs0 += cf[j][0];
            cf[j][1] = __expf(cf[j][1] - m0); rs0 += cf[j][1];
            cf[j][2] = __expf(cf[j][2] - m1); rs1 += cf[j][2];
            cf[j][3] = __expf(cf[j][3] - m1); rs1 += cf[j][3];
        }
        rs0 += __shfl_xor_sync(0xffffffffu, rs0, 1);
        rs0 += __shfl_xor_sync(0xffffffffu, rs0, 2);
        rs1 += __shfl_xor_sync(0xffffffffu, rs1, 1);
        rs1 += __shfl_xor_sync(0xffffffffu, rs1, 2);
        l0 = l0 * alpha0 + rs0;
        l1 = l1 * alpha1 + rs1;

#pragma unroll
        for (int j = 0; j < 8; j++) {
            o[j][0] *= alpha0; o[j][1] *= alpha0;
            o[j][2] *= alpha1; o[j][3] *= alpha1;
        }

        // ---- O += P @ V : assemble P A-fragments via shuffles ----
#pragma unroll
        for (int kk = 0; kk < 8; kk++) {
            float v00 = __shfl_sync(0xffffffffu, cf[kk][0], sl0);
            float v01 = __shfl_sync(0xffffffffu, cf[kk][1], sl0);
            float v20 = __shfl_sync(0xffffffffu, cf[kk][0], sl1);
            float v21 = __shfl_sync(0xffffffffu, cf[kk][1], sl1);
            float v10 = __shfl_sync(0xffffffffu, cf[kk][2], sl0);
            float v11 = __shfl_sync(0xffffffffu, cf[kk][3], sl0);
            float v30 = __shfl_sync(0xffffffffu, cf[kk][2], sl1);
            float v31 = __shfl_sync(0xffffffffu, cf[kk][3], sl1);
            uint32_t pa[4];
            pa[0] = f2tf32(odd ? v01 : v00);
            pa[1] = f2tf32(odd ? v11 : v10);
            pa[2] = f2tf32(odd ? v21 : v20);
            pa[3] = f2tf32(odd ? v31 : v30);
#pragma unroll
            for (int j2 = 0; j2 < 8; j2++) {
                uint32_t b0 = Vs[kk * 8 + qq][j2 * 8 + r];
                uint32_t b1 = Vs[kk * 8 + qq + 4][j2 * 8 + r];
                mma_tf32(o[j2], pa, b0, b1);
            }
        }
        __syncthreads();
    }

    // ---- epilogue ----
    const float inv0 = 1.f / l0;
    const float inv1 = 1.f / l1;
    float* Ob = O + ((size_t)b * SEQ) * DMODEL + h * DHEAD;
    const int row0 = q0 + wm + r;
#pragma unroll
    for (int j2 = 0; j2 < 8; j2++) {
        int col = j2 * 8 + 2 * qq;
        *(float2*)&Ob[(size_t)row0 * DMODEL + col] =
            make_float2(o[j2][0] * inv0, o[j2][1] * inv0);
        *(float2*)&Ob[(size_t)(row0 + 8) * DMODEL + col] =
            make_float2(o[j2][2] * inv1, o[j2][3] * inv1);
    }
}

// ---------------------------------------------------------------------------
// Launch
// ---------------------------------------------------------------------------
extern "C" void kernel_launch(void* const* d_in, const int* in_sizes, int n_in,
                              void* d_out, int out_size)
{
    const float* x  = (const float*)d_in[0];
    const float* Wq = (const float*)d_in[1];
    const float* Wk = (const float*)d_in[2];
    const float* Wv = (const float*)d_in[3];
    const float* Wo = (const float*)d_in[4];
    float* out = (float*)d_out;

    float *q_ptr, *k_ptr, *v_ptr, *attn_ptr;
    uint32_t *xt_ptr, *at_ptr;
    cudaGetSymbolAddress((void**)&q_ptr,    g_q);
    cudaGetSymbolAddress((void**)&k_ptr,    g_k);
    cudaGetSymbolAddress((void**)&v_ptr,    g_v);
    cudaGetSymbolAddress((void**)&attn_ptr, g_attn);
    cudaGetSymbolAddress((void**)&xt_ptr,   g_xt);
    cudaGetSymbolAddress((void**)&at_ptr,   g_at);

    static int smem_set = 0;
    if (!smem_set) {
        cudaFuncSetAttribute(gemm_qkv_kernel,
                             cudaFuncAttributeMaxDynamicSharedMemorySize,
                             GEMM_SMEM_BYTES);
        cudaFuncSetAttribute(gemm_out_kernel,
                             cudaFuncAttributeMaxDynamicSharedMemorySize,
                             GEMM_SMEM_BYTES);
        smem_set = 1;
    }

    // 1. pre-convert x and weights to tf32 bits
    conv_tf32_kernel<<<(MTOT * DMODEL) / (256 * 4), 256>>>(x, xt_ptr);
    conv_w_kernel<<<dim3(WELEM / (256 * 4), 1, 4), 256>>>(Wq, Wk, Wv, Wo);

    // 2. fused Q/K/V projections
    gemm_qkv_kernel<<<dim3(DMODEL / 128, MTOT / 128, 3), 256, GEMM_SMEM_BYTES>>>();

    // 3. flash attention
    dim3 agrid(SEQ / 64, BATCH * NHEAD);
    flash_mma_kernel<<<agrid, 128>>>(q_ptr, k_ptr, v_ptr, attn_ptr);

    // 4. convert attn, output projection
    conv_tf32_kernel<<<(MTOT * DMODEL) / (256 * 4), 256>>>(attn_ptr, at_ptr);
    gemm_out_kernel<<<dim3(DMODEL / 128, MTOT / 128), 256, GEMM_SMEM_BYTES>>>(out);
}

// round 9
// speedup vs baseline: 3.7248x; 1.0448x over previous
#include <cuda_runtime.h>
#include <math.h>
#include <stdint.h>

// Problem constants
#define BATCH 4
#define SEQ   2048
#define DMODEL 1024
#define NHEAD 16
#define DHEAD 64
#define MTOT  (BATCH * SEQ)
#define WELEM (DMODEL * DMODEL)
// attention scale folded with log2(e): softmax computed in log2 domain
#define QSCALE (0.125f * 1.4426950408889634f)

// ---------------------------------------------------------------------------
// Scratch (device globals). q/k/v/attn hold tf32 BIT PATTERNS (uint32).
// ---------------------------------------------------------------------------
__device__ uint32_t g_q[(size_t)MTOT * DMODEL];
__device__ uint32_t g_k[(size_t)MTOT * DMODEL];
__device__ uint32_t g_v[(size_t)MTOT * DMODEL];
__device__ uint32_t g_at[(size_t)MTOT * DMODEL];
__device__ uint32_t g_xt[(size_t)MTOT * DMODEL];
__device__ uint32_t g_wt[(size_t)4 * WELEM];

__device__ __forceinline__ uint32_t f2tf32(float x) {
    uint32_t u;
    asm("cvt.rna.tf32.f32 %0, %1;" : "=r"(u) : "f"(x));
    return u;
}

__device__ __forceinline__ float ex2(float x) {
    float y;
    asm("ex2.approx.ftz.f32 %0, %1;" : "=f"(y) : "f"(x));
    return y;
}

__device__ __forceinline__ void mma_tf32(float c[4], const uint32_t a[4],
                                         uint32_t b0, uint32_t b1) {
    asm volatile(
        "mma.sync.aligned.m16n8k8.row.col.f32.tf32.tf32.f32 "
        "{%0,%1,%2,%3}, {%4,%5,%6,%7}, {%8,%9}, {%0,%1,%2,%3};\n"
        : "+f"(c[0]), "+f"(c[1]), "+f"(c[2]), "+f"(c[3])
        : "r"(a[0]), "r"(a[1]), "r"(a[2]), "r"(a[3]), "r"(b0), "r"(b1));
}

// ---------------------------------------------------------------------------
// fp32 -> tf32-bits conversion kernels
// ---------------------------------------------------------------------------
__global__ __launch_bounds__(256)
void conv_tf32_kernel(const float* __restrict__ in, uint32_t* __restrict__ out)
{
    size_t i = ((size_t)blockIdx.x * 256 + threadIdx.x) * 4;
    float4 v = *(const float4*)&in[i];
    *(uint4*)&out[i] = make_uint4(f2tf32(v.x), f2tf32(v.y), f2tf32(v.z), f2tf32(v.w));
}

__global__ __launch_bounds__(256)
void conv_w_kernel(const float* __restrict__ w0, const float* __restrict__ w1,
                   const float* __restrict__ w2, const float* __restrict__ w3)
{
    const float* src = (blockIdx.z == 0) ? w0 : (blockIdx.z == 1) ? w1
                     : (blockIdx.z == 2) ? w2 : w3;
    size_t i = ((size_t)blockIdx.x * 256 + threadIdx.x) * 4;
    float4 v = *(const float4*)&src[i];
    *(uint4*)&g_wt[(size_t)blockIdx.z * WELEM + i] =
        make_uint4(f2tf32(v.x), f2tf32(v.y), f2tf32(v.z), f2tf32(v.w));
}

// ---------------------------------------------------------------------------
// TF32 GEMM on tf32-bit inputs:  C = A @ W^T
// 128x128 tile, k-tile 16, cp.async double buffer, 8 warps (2m x 4n).
// CVT=true -> write tf32 bits (scaled); CVT=false -> write fp32.
// ---------------------------------------------------------------------------
#define SROW 28
#define TILE_U32 (128 * SROW)
#define GEMM_SMEM_BYTES (4 * TILE_U32 * 4)

template<bool CVT>
__device__ __forceinline__
void gemm_body(uint32_t* smem, const uint32_t* __restrict__ A,
               const uint32_t* __restrict__ W, float* __restrict__ C,
               uint32_t* __restrict__ Ct, float oscale,
               int M, int N, int K, int bm, int bn)
{
    uint32_t* As = smem;
    uint32_t* Bs = smem + 2 * TILE_U32;

    const int tid = threadIdx.x;
    const int lane = tid & 31;
    const int warp = tid >> 5;
    const int wm = (warp >> 2) * 64;
    const int wn = (warp & 3) * 32;

    const uint32_t s_as = (uint32_t)__cvta_generic_to_shared(As);
    const uint32_t s_bs = (uint32_t)__cvta_generic_to_shared(Bs);

    float c[4][4][4];
#pragma unroll
    for (int i = 0; i < 4; i++)
#pragma unroll
        for (int j = 0; j < 4; j++)
#pragma unroll
            for (int r = 0; r < 4; r++) c[i][j][r] = 0.f;

    const int NT = K / 16;

    auto cp_tile = [&](int kt, int buf) {
        const int k0 = kt * 16;
        const uint32_t abase = s_as + (uint32_t)(buf * TILE_U32) * 4u;
        const uint32_t bbase = s_bs + (uint32_t)(buf * TILE_U32) * 4u;
#pragma unroll
        for (int l = 0; l < 2; l++) {
            int idx = tid + l * 256;
            int r = idx >> 2;
            int c4 = (idx & 3) * 4;
            uint32_t da = abase + (uint32_t)(r * SROW + c4) * 4u;
            const uint32_t* ga = &A[(size_t)(bm + r) * K + k0 + c4];
            asm volatile("cp.async.ca.shared.global [%0], [%1], 16;\n"
                         :: "r"(da), "l"(ga));
            uint32_t db = bbase + (uint32_t)(r * SROW + c4) * 4u;
            const uint32_t* gb = &W[(size_t)(bn + r) * K + k0 + c4];
            asm volatile("cp.async.ca.shared.global [%0], [%1], 16;\n"
                         :: "r"(db), "l"(gb));
        }
        asm volatile("cp.async.commit_group;\n" ::: "memory");
    };

    cp_tile(0, 0);

    for (int kt = 0; kt < NT; kt++) {
        const int buf = kt & 1;
        asm volatile("cp.async.wait_group 0;\n" ::: "memory");
        __syncthreads();
        if (kt + 1 < NT) cp_tile(kt + 1, buf ^ 1);

        const uint32_t* as = As + buf * TILE_U32;
        const uint32_t* bs = Bs + buf * TILE_U32;

#pragma unroll
        for (int s = 0; s < 2; s++) {
            const int kb = s * 8 + (lane & 3);
            uint32_t a[4][4], b[4][2];
#pragma unroll
            for (int i = 0; i < 4; i++) {
                const uint32_t* p = as + (wm + i * 16 + (lane >> 2)) * SROW + kb;
                a[i][0] = p[0];
                a[i][2] = p[4];
                const uint32_t* p8 = p + 8 * SROW;
                a[i][1] = p8[0];
                a[i][3] = p8[4];
            }
#pragma unroll
            for (int j = 0; j < 4; j++) {
                const uint32_t* p = bs + (wn + j * 8 + (lane >> 2)) * SROW + kb;
                b[j][0] = p[0];
                b[j][1] = p[4];
            }
#pragma unroll
            for (int i = 0; i < 4; i++)
#pragma unroll
                for (int j = 0; j < 4; j++)
                    mma_tf32(c[i][j], a[i], b[j][0], b[j][1]);
        }
        __syncthreads();
    }

#pragma unroll
    for (int i = 0; i < 4; i++) {
#pragma unroll
        for (int j = 0; j < 4; j++) {
            int row = bm + wm + i * 16 + (lane >> 2);
            int col = bn + wn + j * 8 + (lane & 3) * 2;
            if (CVT) {
                *(uint2*)&Ct[(size_t)row * N + col] =
                    make_uint2(f2tf32(c[i][j][0] * oscale), f2tf32(c[i][j][1] * oscale));
                *(uint2*)&Ct[(size_t)(row + 8) * N + col] =
                    make_uint2(f2tf32(c[i][j][2] * oscale), f2tf32(c[i][j][3] * oscale));
            } else {
                *(float2*)&C[(size_t)row * N + col] =
                    make_float2(c[i][j][0], c[i][j][1]);
                *(float2*)&C[(size_t)(row + 8) * N + col] =
                    make_float2(c[i][j][2], c[i][j][3]);
            }
        }
    }
}

// Fused Q/K/V projection. Q pre-scaled by QSCALE (attention scale * log2e).
__global__ __launch_bounds__(256, 2)
void gemm_qkv_kernel()
{
    extern __shared__ uint32_t smem[];
    const int z = blockIdx.z;
    uint32_t* Ct = (z == 0) ? g_q : (z == 1) ? g_k : g_v;
    float oscale = (z == 0) ? QSCALE : 1.0f;
    gemm_body<true>(smem, g_xt, g_wt + (size_t)z * WELEM, nullptr, Ct, oscale,
                    MTOT, DMODEL, DMODEL, blockIdx.y * 128, blockIdx.x * 128);
}

__global__ __launch_bounds__(256, 2)
void gemm_out_kernel(float* __restrict__ out)
{
    extern __shared__ uint32_t smem[];
    gemm_body<false>(smem, g_at, g_wt + (size_t)3 * WELEM, out, nullptr, 1.0f,
                     MTOT, DMODEL, DMODEL, blockIdx.y * 128, blockIdx.x * 128);
}

// ---------------------------------------------------------------------------
// Tensor-core causal flash attention.
// 256 threads = 8 warps, Q tile 128 (warp = 16 rows), KV tile 64.
// All inputs are tf32 bits; cp.async double-buffered K/V; zero cvt in loop.
// Softmax in log2 domain (ex2.approx). Output written as tf32 bits to g_at.
// ---------------------------------------------------------------------------
#define KSTR 68
#define VSTR 72
#define FLASH_SMEM ((2 * 64 * KSTR + 2 * 64 * VSTR) * 4)   // 71680 B

__global__ __launch_bounds__(256, 2)
void flash_mma_kernel(const uint32_t* __restrict__ Q, const uint32_t* __restrict__ K,
                      const uint32_t* __restrict__ V, uint32_t* __restrict__ O)
{
    extern __shared__ uint32_t sm[];
    uint32_t* KsB = sm;                       // [2][64][KSTR]; Q staging: [128][KSTR]
    uint32_t* VsB = sm + 2 * 64 * KSTR;       // [2][64][VSTR]

    const int bh = blockIdx.y;
    const int b = bh >> 4;
    const int h = bh & 15;
    const int qb = gridDim.x - 1 - blockIdx.x;   // heavy blocks first
    const int q0 = qb * 128;
    const int tid = threadIdx.x;
    const int lane = tid & 31;
    const int warp = tid >> 5;                   // 0..7
    const int wm = warp * 16;
    const int r = lane >> 2;
    const int qq = lane & 3;

    const uint32_t* Qb = Q + ((size_t)b * SEQ) * DMODEL + h * DHEAD;
    const uint32_t* Kb = K + ((size_t)b * SEQ) * DMODEL + h * DHEAD;
    const uint32_t* Vb = V + ((size_t)b * SEQ) * DMODEL + h * DHEAD;

    // ---- Stage Q tile (128 rows x 64 tf32 words) through KsB ----
#pragma unroll
    for (int i = 0; i < 8; i++) {
        int idx = tid + i * 256;                 // 0..2047
        int rr = idx >> 4;
        int cc = (idx & 15) * 4;
        *(uint4*)&KsB[rr * KSTR + cc] = *(const uint4*)&Qb[(size_t)(q0 + rr) * DMODEL + cc];
    }
    __syncthreads();

    uint32_t qf[8][4];
#pragma unroll
    for (int kk = 0; kk < 8; kk++) {
        qf[kk][0] = KsB[(wm + r) * KSTR + kk * 8 + qq];
        qf[kk][1] = KsB[(wm + r + 8) * KSTR + kk * 8 + qq];
        qf[kk][2] = KsB[(wm + r) * KSTR + kk * 8 + qq + 4];
        qf[kk][3] = KsB[(wm + r + 8) * KSTR + kk * 8 + qq + 4];
    }
    __syncthreads();

    float o[8][4];
#pragma unroll
    for (int j = 0; j < 8; j++)
#pragma unroll
        for (int x = 0; x < 4; x++) o[j][x] = 0.f;
    float m0 = -INFINITY, m1 = -INFINITY;
    float l0 = 0.f, l1 = 0.f;

    const int base = lane & 28;
    const int sl0 = base + (qq >> 1);
    const int sl1 = sl0 + 2;
    const bool odd = (qq & 1);

    const int nt = 2 * qb + 2;                    // KV tiles of 64 covering [0, q0+128)
    const uint32_t s_k = (uint32_t)__cvta_generic_to_shared(KsB);
    const uint32_t s_v = (uint32_t)__cvta_generic_to_shared(VsB);

    auto cp_tile = [&](int t, int buf) {
        const int k0 = t * 64;
        const uint32_t kb = s_k + (uint32_t)(buf * 64 * KSTR) * 4u;
        const uint32_t vb = s_v + (uint32_t)(buf * 64 * VSTR) * 4u;
#pragma unroll
        for (int l = 0; l < 4; l++) {
            int idx = tid + l * 256;              // 0..1023
            int rr = idx >> 4;
            int cc = (idx & 15) * 4;
            uint32_t dk = kb + (uint32_t)(rr * KSTR + cc) * 4u;
            const uint32_t* gk = &Kb[(size_t)(k0 + rr) * DMODEL + cc];
            asm volatile("cp.async.ca.shared.global [%0], [%1], 16;\n"
                         :: "r"(dk), "l"(gk));
            uint32_t dv = vb + (uint32_t)(rr * VSTR + cc) * 4u;
            const uint32_t* gv = &Vb[(size_t)(k0 + rr) * DMODEL + cc];
            asm volatile("cp.async.ca.shared.global [%0], [%1], 16;\n"
                         :: "r"(dv), "l"(gv));
        }
        asm volatile("cp.async.commit_group;\n" ::: "memory");
    };

    cp_tile(0, 0);

    for (int t = 0; t < nt; t++) {
        if (t + 1 < nt) {
            cp_tile(t + 1, (t + 1) & 1);
            asm volatile("cp.async.wait_group 1;\n" ::: "memory");
        } else {
            asm volatile("cp.async.wait_group 0;\n" ::: "memory");
        }
        __syncthreads();

        const uint32_t* ks = KsB + (t & 1) * 64 * KSTR;
        const uint32_t* vs = VsB + (t & 1) * 64 * VSTR;
        const int k0 = t * 64;

        // warp-uniform early-out: all 16 rows of this warp fully masked
        if (k0 <= q0 + wm + 15) {
            // ---- S = Q @ K^T ----
            float cf[8][4];
#pragma unroll
            for (int j = 0; j < 8; j++) {
#pragma unroll
                for (int x = 0; x < 4; x++) cf[j][x] = 0.f;
#pragma unroll
                for (int kk = 0; kk < 8; kk++) {
                    uint32_t b0 = ks[(j * 8 + r) * KSTR + kk * 8 + qq];
                    uint32_t b1 = ks[(j * 8 + r) * KSTR + kk * 8 + qq + 4];
                    mma_tf32(cf[j], qf[kk], b0, b1);
                }
            }

            // ---- causal mask (global indices) on the two diagonal tiles ----
            if (t >= nt - 2) {
                const int row0 = q0 + wm + r;
                const int row1 = row0 + 8;
#pragma unroll
                for (int j = 0; j < 8; j++) {
                    int kc = k0 + j * 8 + 2 * qq;
                    if (kc > row0)     cf[j][0] = -INFINITY;
                    if (kc + 1 > row0) cf[j][1] = -INFINITY;
                    if (kc > row1)     cf[j][2] = -INFINITY;
                    if (kc + 1 > row1) cf[j][3] = -INFINITY;
                }
            }

            // ---- online softmax (log2 domain) ----
            float t0 = -INFINITY, t1 = -INFINITY;
#pragma unroll
            for (int j = 0; j < 8; j++) {
                t0 = fmaxf(t0, fmaxf(cf[j][0], cf[j][1]));
                t1 = fmaxf(t1, fmaxf(cf[j][2], cf[j][3]));
            }
            t0 = fmaxf(t0, __shfl_xor_sync(0xffffffffu, t0, 1));
            t0 = fmaxf(t0, __shfl_xor_sync(0xffffffffu, t0, 2));
            t1 = fmaxf(t1, __shfl_xor_sync(0xffffffffu, t1, 1));
            t1 = fmaxf(t1, __shfl_xor_sync(0xffffffffu, t1, 2));

            float nm0 = fmaxf(m0, t0);
            float nm1 = fmaxf(m1, t1);
            float alpha0 = ex2(m0 - nm0);
            float alpha1 = ex2(m1 - nm1);
            m0 = nm0; m1 = nm1;

            float rs0 = 0.f, rs1 = 0.f;
#pragma unroll
            for (int j = 0; j < 8; j++) {
                cf[j][0] = ex2(cf[j][0] - m0); rs0 += cf[j][0];
                cf[j][1] = ex2(cf[j][1] - m0); rs0 += cf[j][1];
                cf[j][2] = ex2(cf[j][2] - m1); rs1 += cf[j][2];
                cf[j][3] = ex2(cf[j][3] - m1); rs1 += cf[j][3];
            }
            rs0 += __shfl_xor_sync(0xffffffffu, rs0, 1);
            rs0 += __shfl_xor_sync(0xffffffffu, rs0, 2);
            rs1 += __shfl_xor_sync(0xffffffffu, rs1, 1);
            rs1 += __shfl_xor_sync(0xffffffffu, rs1, 2);
            l0 = l0 * alpha0 + rs0;
            l1 = l1 * alpha1 + rs1;

#pragma unroll
            for (int j = 0; j < 8; j++) {
                o[j][0] *= alpha0; o[j][1] *= alpha0;
                o[j][2] *= alpha1; o[j][3] *= alpha1;
            }

            // ---- O += P @ V (P A-fragments via shuffles) ----
#pragma unroll
            for (int kk = 0; kk < 8; kk++) {
                float v00 = __shfl_sync(0xffffffffu, cf[kk][0], sl0);
                float v01 = __shfl_sync(0xffffffffu, cf[kk][1], sl0);
                float v20 = __shfl_sync(0xffffffffu, cf[kk][0], sl1);
                float v21 = __shfl_sync(0xffffffffu, cf[kk][1], sl1);
                float v10 = __shfl_sync(0xffffffffu, cf[kk][2], sl0);
                float v11 = __shfl_sync(0xffffffffu, cf[kk][3], sl0);
                float v30 = __shfl_sync(0xffffffffu, cf[kk][2], sl1);
                float v31 = __shfl_sync(0xffffffffu, cf[kk][3], sl1);
                uint32_t pa[4];
                pa[0] = f2tf32(odd ? v01 : v00);
                pa[1] = f2tf32(odd ? v11 : v10);
                pa[2] = f2tf32(odd ? v21 : v20);
                pa[3] = f2tf32(odd ? v31 : v30);
#pragma unroll
                for (int j2 = 0; j2 < 8; j2++) {
                    uint32_t b0 = vs[(kk * 8 + qq) * VSTR + j2 * 8 + r];
                    uint32_t b1 = vs[(kk * 8 + qq + 4) * VSTR + j2 * 8 + r];
                    mma_tf32(o[j2], pa, b0, b1);
                }
            }
        }
        __syncthreads();
    }

    // ---- epilogue: normalize, convert to tf32 bits, store ----
    const float inv0 = 1.f / l0;
    const float inv1 = 1.f / l1;
    uint32_t* Ob = O + ((size_t)b * SEQ) * DMODEL + h * DHEAD;
    const int row0 = q0 + wm + r;
#pragma unroll
    for (int j2 = 0; j2 < 8; j2++) {
        int col = j2 * 8 + 2 * qq;
        *(uint2*)&Ob[(size_t)row0 * DMODEL + col] =
            make_uint2(f2tf32(o[j2][0] * inv0), f2tf32(o[j2][1] * inv0));
        *(uint2*)&Ob[(size_t)(row0 + 8) * DMODEL + col] =
            make_uint2(f2tf32(o[j2][2] * inv1), f2tf32(o[j2][3] * inv1));
    }
}

// ---------------------------------------------------------------------------
// Launch
// ---------------------------------------------------------------------------
extern "C" void kernel_launch(void* const* d_in, const int* in_sizes, int n_in,
                              void* d_out, int out_size)
{
    const float* x  = (const float*)d_in[0];
    const float* Wq = (const float*)d_in[1];
    const float* Wk = (const float*)d_in[2];
    const float* Wv = (const float*)d_in[3];
    const float* Wo = (const float*)d_in[4];
    float* out = (float*)d_out;

    uint32_t *q_ptr, *k_ptr, *v_ptr, *at_ptr, *xt_ptr;
    cudaGetSymbolAddress((void**)&q_ptr,  g_q);
    cudaGetSymbolAddress((void**)&k_ptr,  g_k);
    cudaGetSymbolAddress((void**)&v_ptr,  g_v);
    cudaGetSymbolAddress((void**)&at_ptr, g_at);
    cudaGetSymbolAddress((void**)&xt_ptr, g_xt);

    static int attr_set = 0;
    if (!attr_set) {
        cudaFuncSetAttribute(gemm_qkv_kernel,
                             cudaFuncAttributeMaxDynamicSharedMemorySize,
                             GEMM_SMEM_BYTES);
        cudaFuncSetAttribute(gemm_out_kernel,
                             cudaFuncAttributeMaxDynamicSharedMemorySize,
                             GEMM_SMEM_BYTES);
        cudaFuncSetAttribute(flash_mma_kernel,
                             cudaFuncAttributeMaxDynamicSharedMemorySize,
                             FLASH_SMEM);
        attr_set = 1;
    }

    // 1. pre-convert x and weights to tf32 bits
    conv_tf32_kernel<<<(MTOT * DMODEL) / (256 * 4), 256>>>(x, xt_ptr);
    conv_w_kernel<<<dim3(WELEM / (256 * 4), 1, 4), 256>>>(Wq, Wk, Wv, Wo);

    // 2. fused Q/K/V projections (outputs tf32 bits; Q pre-scaled)
    gemm_qkv_kernel<<<dim3(DMODEL / 128, MTOT / 128, 3), 256, GEMM_SMEM_BYTES>>>();

    // 3. flash attention (tf32 in, tf32 out)
    dim3 agrid(SEQ / 128, BATCH * NHEAD);   // (16, 64)
    flash_mma_kernel<<<agrid, 256, FLASH_SMEM>>>(q_ptr, k_ptr, v_ptr, at_ptr);

    // 4. output projection
    gemm_out_kernel<<<dim3(DMODEL / 128, MTOT / 128), 256, GEMM_SMEM_BYTES>>>(out);
}

// round 10
// speedup vs baseline: 3.9176x; 1.0517x over previous
#include <cuda_runtime.h>
#include <math.h>
#include <stdint.h>

// Problem constants
#define BATCH 4
#define SEQ   2048
#define DMODEL 1024
#define NHEAD 16
#define DHEAD 64
#define MTOT  (BATCH * SEQ)
#define WELEM (DMODEL * DMODEL)
// attention scale folded with log2(e): softmax computed in log2 domain
#define QSCALE (0.125f * 1.4426950408889634f)

// ---------------------------------------------------------------------------
// Scratch (device globals). q/k/v/attn hold tf32 BIT PATTERNS (uint32).
// ---------------------------------------------------------------------------
__device__ uint32_t g_q[(size_t)MTOT * DMODEL];
__device__ uint32_t g_k[(size_t)MTOT * DMODEL];
__device__ uint32_t g_v[(size_t)MTOT * DMODEL];
__device__ uint32_t g_at[(size_t)MTOT * DMODEL];
__device__ uint32_t g_xt[(size_t)MTOT * DMODEL];
__device__ uint32_t g_wt[(size_t)4 * WELEM];

__device__ __forceinline__ uint32_t f2tf32(float x) {
    uint32_t u;
    asm("cvt.rna.tf32.f32 %0, %1;" : "=r"(u) : "f"(x));
    return u;
}

__device__ __forceinline__ float ex2(float x) {
    float y;
    asm("ex2.approx.ftz.f32 %0, %1;" : "=f"(y) : "f"(x));
    return y;
}

__device__ __forceinline__ void mma_tf32(float c[4], const uint32_t a[4],
                                         uint32_t b0, uint32_t b1) {
    asm volatile(
        "mma.sync.aligned.m16n8k8.row.col.f32.tf32.tf32.f32 "
        "{%0,%1,%2,%3}, {%4,%5,%6,%7}, {%8,%9}, {%0,%1,%2,%3};\n"
        : "+f"(c[0]), "+f"(c[1]), "+f"(c[2]), "+f"(c[3])
        : "r"(a[0]), "r"(a[1]), "r"(a[2]), "r"(a[3]), "r"(b0), "r"(b1));
}

// ---------------------------------------------------------------------------
// fp32 -> tf32-bits conversion kernels
// ---------------------------------------------------------------------------
__global__ __launch_bounds__(256)
void conv_tf32_kernel(const float* __restrict__ in, uint32_t* __restrict__ out)
{
    size_t i = ((size_t)blockIdx.x * 256 + threadIdx.x) * 4;
    float4 v = *(const float4*)&in[i];
    *(uint4*)&out[i] = make_uint4(f2tf32(v.x), f2tf32(v.y), f2tf32(v.z), f2tf32(v.w));
}

__global__ __launch_bounds__(256)
void conv_w_kernel(const float* __restrict__ w0, const float* __restrict__ w1,
                   const float* __restrict__ w2, const float* __restrict__ w3)
{
    const float* src = (blockIdx.z == 0) ? w0 : (blockIdx.z == 1) ? w1
                     : (blockIdx.z == 2) ? w2 : w3;
    size_t i = ((size_t)blockIdx.x * 256 + threadIdx.x) * 4;
    float4 v = *(const float4*)&src[i];
    *(uint4*)&g_wt[(size_t)blockIdx.z * WELEM + i] =
        make_uint4(f2tf32(v.x), f2tf32(v.y), f2tf32(v.z), f2tf32(v.w));
}

// ---------------------------------------------------------------------------
// TF32 GEMM on tf32-bit inputs:  C = A @ W^T
// 128x128 tile, K-TILE 32, 3-STAGE cp.async pipeline, 8 warps (2m x 4n).
// Row stride 36 words (144B): 16B-aligned for cp.async; 36 = 4 mod 32 keeps
// fragment LDS conflict-free ((4r+qq) distinct over the warp).
// One barrier per k-tile; cp for tile t+2 issued right after it, so two full
// tiles of MMA hide each load.
// ---------------------------------------------------------------------------
#define GKT   32
#define GSROW 36
#define GTILE_U32 (128 * GSROW)                     // 4608 words / matrix / stage
#define GEMM_SMEM_BYTES (6 * GTILE_U32 * 4)         // 2 matrices x 3 stages = 110592

template<bool CVT>
__device__ __forceinline__
void gemm_body(uint32_t* smem, const uint32_t* __restrict__ A,
               const uint32_t* __restrict__ W, float* __restrict__ C,
               uint32_t* __restrict__ Ct, float oscale,
               int M, int N, int K, int bm, int bn)
{
    uint32_t* As = smem;                    // [3][128*GSROW]
    uint32_t* Bs = smem + 3 * GTILE_U32;    // [3][128*GSROW]

    const int tid = threadIdx.x;
    const int lane = tid & 31;
    const int warp = tid >> 5;
    const int wm = (warp >> 2) * 64;
    const int wn = (warp & 3) * 32;
    const int r = lane >> 2;
    const int qq = lane & 3;

    const uint32_t s_as = (uint32_t)__cvta_generic_to_shared(As);
    const uint32_t s_bs = (uint32_t)__cvta_generic_to_shared(Bs);

    float c[4][4][4];
#pragma unroll
    for (int i = 0; i < 4; i++)
#pragma unroll
        for (int j = 0; j < 4; j++)
#pragma unroll
            for (int x = 0; x < 4; x++) c[i][j][x] = 0.f;

    const int NT = K / GKT;                 // 32

    auto cp_tile = [&](int kt, int buf) {
        const int k0 = kt * GKT;
        const uint32_t abase = s_as + (uint32_t)(buf * GTILE_U32) * 4u;
        const uint32_t bbase = s_bs + (uint32_t)(buf * GTILE_U32) * 4u;
#pragma unroll
        for (int l = 0; l < 4; l++) {
            int idx = tid + l * 256;            // 0..1023 float4 chunks
            int rr = idx >> 3;                  // 0..127
            int c4 = (idx & 7) * 4;             // 0..28
            uint32_t da = abase + (uint32_t)(rr * GSROW + c4) * 4u;
            const uint32_t* ga = &A[(size_t)(bm + rr) * K + k0 + c4];
            asm volatile("cp.async.ca.shared.global [%0], [%1], 16;\n"
                         :: "r"(da), "l"(ga));
            uint32_t db = bbase + (uint32_t)(rr * GSROW + c4) * 4u;
            const uint32_t* gb = &W[(size_t)(bn + rr) * K + k0 + c4];
            asm volatile("cp.async.ca.shared.global [%0], [%1], 16;\n"
                         :: "r"(db), "l"(gb));
        }
        asm volatile("cp.async.commit_group;\n" ::: "memory");
    };

    cp_tile(0, 0);
    cp_tile(1, 1);

    for (int kt = 0; kt < NT; kt++) {
        if (kt + 1 < NT)
            asm volatile("cp.async.wait_group 1;\n" ::: "memory");
        else
            asm volatile("cp.async.wait_group 0;\n" ::: "memory");
        __syncthreads();
        if (kt + 2 < NT) {
            int b2 = kt + 2;
            cp_tile(b2, b2 % 3);
        }

        const uint32_t* as = As + (kt % 3) * GTILE_U32;
        const uint32_t* bs = Bs + (kt % 3) * GTILE_U32;

#pragma unroll
        for (int s = 0; s < 4; s++) {
            const int kb = s * 8 + qq;
            uint32_t a[4][4], b[4][2];
#pragma unroll
            for (int i = 0; i < 4; i++) {
                const uint32_t* p = as + (wm + i * 16 + r) * GSROW + kb;
                a[i][0] = p[0];
                a[i][2] = p[4];
                const uint32_t* p8 = p + 8 * GSROW;
                a[i][1] = p8[0];
                a[i][3] = p8[4];
            }
#pragma unroll
            for (int j = 0; j < 4; j++) {
                const uint32_t* p = bs + (wn + j * 8 + r) * GSROW + kb;
                b[j][0] = p[0];
                b[j][1] = p[4];
            }
#pragma unroll
            for (int i = 0; i < 4; i++)
#pragma unroll
                for (int j = 0; j < 4; j++)
                    mma_tf32(c[i][j], a[i], b[j][0], b[j][1]);
        }
    }
    __syncthreads();

#pragma unroll
    for (int i = 0; i < 4; i++) {
#pragma unroll
        for (int j = 0; j < 4; j++) {
            int row = bm + wm + i * 16 + r;
            int col = bn + wn + j * 8 + qq * 2;
            if (CVT) {
                *(uint2*)&Ct[(size_t)row * N + col] =
                    make_uint2(f2tf32(c[i][j][0] * oscale), f2tf32(c[i][j][1] * oscale));
                *(uint2*)&Ct[(size_t)(row + 8) * N + col] =
                    make_uint2(f2tf32(c[i][j][2] * oscale), f2tf32(c[i][j][3] * oscale));
            } else {
                *(float2*)&C[(size_t)row * N + col] =
                    make_float2(c[i][j][0], c[i][j][1]);
                *(float2*)&C[(size_t)(row + 8) * N + col] =
                    make_float2(c[i][j][2], c[i][j][3]);
            }
        }
    }
}

// Fused Q/K/V projection. Q pre-scaled by QSCALE (attention scale * log2e).
__global__ __launch_bounds__(256, 2)
void gemm_qkv_kernel()
{
    extern __shared__ uint32_t smem[];
    const int z = blockIdx.z;
    uint32_t* Ct = (z == 0) ? g_q : (z == 1) ? g_k : g_v;
    float oscale = (z == 0) ? QSCALE : 1.0f;
    gemm_body<true>(smem, g_xt, g_wt + (size_t)z * WELEM, nullptr, Ct, oscale,
                    MTOT, DMODEL, DMODEL, blockIdx.y * 128, blockIdx.x * 128);
}

__global__ __launch_bounds__(256, 2)
void gemm_out_kernel(float* __restrict__ out)
{
    extern __shared__ uint32_t smem[];
    gemm_body<false>(smem, g_at, g_wt + (size_t)3 * WELEM, out, nullptr, 1.0f,
                     MTOT, DMODEL, DMODEL, blockIdx.y * 128, blockIdx.x * 128);
}

// ---------------------------------------------------------------------------
// Tensor-core causal flash attention.
// 256 threads = 8 warps, Q tile 128 (warp = 16 rows), KV tile 64.
// 3-STAGE cp.async K/V pipeline: wait -> barrier -> issue t+2 -> compute t.
// Softmax in log2 domain (ex2.approx). All data tf32 bits; zero cvt in loop.
// ---------------------------------------------------------------------------
#define KSTR 68
#define VSTR 72
#define FLASH_SMEM ((3 * 64 * KSTR + 3 * 64 * VSTR) * 4)   // 107520 B

__global__ __launch_bounds__(256, 2)
void flash_mma_kernel(const uint32_t* __restrict__ Q, const uint32_t* __restrict__ K,
                      const uint32_t* __restrict__ V, uint32_t* __restrict__ O)
{
    extern __shared__ uint32_t sm[];
    uint32_t* KsB = sm;                       // [3][64][KSTR]; Q staging: [128][KSTR]
    uint32_t* VsB = sm + 3 * 64 * KSTR;       // [3][64][VSTR]

    const int bh = blockIdx.y;
    const int b = bh >> 4;
    const int h = bh & 15;
    const int qb = gridDim.x - 1 - blockIdx.x;   // heavy blocks first
    const int q0 = qb * 128;
    const int tid = threadIdx.x;
    const int lane = tid & 31;
    const int warp = tid >> 5;                   // 0..7
    const int wm = warp * 16;
    const int r = lane >> 2;
    const int qq = lane & 3;

    const uint32_t* Qb = Q + ((size_t)b * SEQ) * DMODEL + h * DHEAD;
    const uint32_t* Kb = K + ((size_t)b * SEQ) * DMODEL + h * DHEAD;
    const uint32_t* Vb = V + ((size_t)b * SEQ) * DMODEL + h * DHEAD;

    // ---- Stage Q tile (128 rows x 64 words) through KsB, extract fragments ----
#pragma unroll
    for (int i = 0; i < 8; i++) {
        int idx = tid + i * 256;                 // 0..2047
        int rr = idx >> 4;
        int cc = (idx & 15) * 4;
        *(uint4*)&KsB[rr * KSTR + cc] = *(const uint4*)&Qb[(size_t)(q0 + rr) * DMODEL + cc];
    }
    __syncthreads();

    uint32_t qf[8][4];
#pragma unroll
    for (int kk = 0; kk < 8; kk++) {
        qf[kk][0] = KsB[(wm + r) * KSTR + kk * 8 + qq];
        qf[kk][1] = KsB[(wm + r + 8) * KSTR + kk * 8 + qq];
        qf[kk][2] = KsB[(wm + r) * KSTR + kk * 8 + qq + 4];
        qf[kk][3] = KsB[(wm + r + 8) * KSTR + kk * 8 + qq + 4];
    }
    __syncthreads();

    float o[8][4];
#pragma unroll
    for (int j = 0; j < 8; j++)
#pragma unroll
        for (int x = 0; x < 4; x++) o[j][x] = 0.f;
    float m0 = -INFINITY, m1 = -INFINITY;
    float l0 = 0.f, l1 = 0.f;

    const int base = lane & 28;
    const int sl0 = base + (qq >> 1);
    const int sl1 = sl0 + 2;
    const bool odd = (qq & 1);

    const int nt = 2 * qb + 2;                    // KV tiles of 64 covering [0, q0+128)
    const uint32_t s_k = (uint32_t)__cvta_generic_to_shared(KsB);
    const uint32_t s_v = (uint32_t)__cvta_generic_to_shared(VsB);

    auto cp_tile = [&](int t, int buf) {
        const int k0 = t * 64;
        const uint32_t kb = s_k + (uint32_t)(buf * 64 * KSTR) * 4u;
        const uint32_t vb = s_v + (uint32_t)(buf * 64 * VSTR) * 4u;
#pragma unroll
        for (int l = 0; l < 4; l++) {
            int idx = tid + l * 256;              // 0..1023
            int rr = idx >> 4;
            int cc = (idx & 15) * 4;
            uint32_t dk = kb + (uint32_t)(rr * KSTR + cc) * 4u;
            const uint32_t* gk = &Kb[(size_t)(k0 + rr) * DMODEL + cc];
            asm volatile("cp.async.ca.shared.global [%0], [%1], 16;\n"
                         :: "r"(dk), "l"(gk));
            uint32_t dv = vb + (uint32_t)(rr * VSTR + cc) * 4u;
            const uint32_t* gv = &Vb[(size_t)(k0 + rr) * DMODEL + cc];
            asm volatile("cp.async.ca.shared.global [%0], [%1], 16;\n"
                         :: "r"(dv), "l"(gv));
        }
        asm volatile("cp.async.commit_group;\n" ::: "memory");
    };

    cp_tile(0, 0);
    if (nt > 1) cp_tile(1, 1);

    for (int t = 0; t < nt; t++) {
        if (t + 1 < nt)
            asm volatile("cp.async.wait_group 1;\n" ::: "memory");
        else
            asm volatile("cp.async.wait_group 0;\n" ::: "memory");
        __syncthreads();
        if (t + 2 < nt) cp_tile(t + 2, (t + 2) % 3);

        const uint32_t* ks = KsB + (t % 3) * 64 * KSTR;
        const uint32_t* vs = VsB + (t % 3) * 64 * VSTR;
        const int k0 = t * 64;

        // warp-uniform early-out: all 16 rows of this warp fully masked
        if (k0 <= q0 + wm + 15) {
            // ---- S = Q @ K^T ----
            float cf[8][4];
#pragma unroll
            for (int j = 0; j < 8; j++) {
#pragma unroll
                for (int x = 0; x < 4; x++) cf[j][x] = 0.f;
#pragma unroll
                for (int kk = 0; kk < 8; kk++) {
                    uint32_t b0 = ks[(j * 8 + r) * KSTR + kk * 8 + qq];
                    uint32_t b1 = ks[(j * 8 + r) * KSTR + kk * 8 + qq + 4];
                    mma_tf32(cf[j], qf[kk], b0, b1);
                }
            }

            // ---- causal mask (global indices) on the two diagonal tiles ----
            if (t >= nt - 2) {
                const int row0 = q0 + wm + r;
                const int row1 = row0 + 8;
#pragma unroll
                for (int j = 0; j < 8; j++) {
                    int kc = k0 + j * 8 + 2 * qq;
                    if (kc > row0)     cf[j][0] = -INFINITY;
                    if (kc + 1 > row0) cf[j][1] = -INFINITY;
                    if (kc > row1)     cf[j][2] = -INFINITY;
                    if (kc + 1 > row1) cf[j][3] = -INFINITY;
                }
            }

            // ---- online softmax (log2 domain) ----
            float t0 = -INFINITY, t1 = -INFINITY;
#pragma unroll
            for (int j = 0; j < 8; j++) {
                t0 = fmaxf(t0, fmaxf(cf[j][0], cf[j][1]));
                t1 = fmaxf(t1, fmaxf(cf[j][2], cf[j][3]));
            }
            t0 = fmaxf(t0, __shfl_xor_sync(0xffffffffu, t0, 1));
            t0 = fmaxf(t0, __shfl_xor_sync(0xffffffffu, t0, 2));
            t1 = fmaxf(t1, __shfl_xor_sync(0xffffffffu, t1, 1));
            t1 = fmaxf(t1, __shfl_xor_sync(0xffffffffu, t1, 2));

            float nm0 = fmaxf(m0, t0);
            float nm1 = fmaxf(m1, t1);
            float alpha0 = ex2(m0 - nm0);
            float alpha1 = ex2(m1 - nm1);
            m0 = nm0; m1 = nm1;

            float rs0 = 0.f, rs1 = 0.f;
#pragma unroll
            for (int j = 0; j < 8; j++) {
                cf[j][0] = ex2(cf[j][0] - m0); rs0 += cf[j][0];
                cf[j][1] = ex2(cf[j][1] - m0); rs0 += cf[j][1];
                cf[j][2] = ex2(cf[j][2] - m1); rs1 += cf[j][2];
                cf[j][3] = ex2(cf[j][3] - m1); rs1 += cf[j][3];
            }
            rs0 += __shfl_xor_sync(0xffffffffu, rs0, 1);
            rs0 += __shfl_xor_sync(0xffffffffu, rs0, 2);
            rs1 += __shfl_xor_sync(0xffffffffu, rs1, 1);
            rs1 += __shfl_xor_sync(0xffffffffu, rs1, 2);
            l0 = l0 * alpha0 + rs0;
            l1 = l1 * alpha1 + rs1;

#pragma unroll
            for (int j = 0; j < 8; j++) {
                o[j][0] *= alpha0; o[j][1] *= alpha0;
                o[j][2] *= alpha1; o[j][3] *= alpha1;
            }

            // ---- O += P @ V (P A-fragments via shuffles) ----
#pragma unroll
            for (int kk = 0; kk < 8; kk++) {
                float v00 = __shfl_sync(0xffffffffu, cf[kk][0], sl0);
                float v01 = __shfl_sync(0xffffffffu, cf[kk][1], sl0);
                float v20 = __shfl_sync(0xffffffffu, cf[kk][0], sl1);
                float v21 = __shfl_sync(0xffffffffu, cf[kk][1], sl1);
                float v10 = __shfl_sync(0xffffffffu, cf[kk][2], sl0);
                float v11 = __shfl_sync(0xffffffffu, cf[kk][3], sl0);
                float v30 = __shfl_sync(0xffffffffu, cf[kk][2], sl1);
                float v31 = __shfl_sync(0xffffffffu, cf[kk][3], sl1);
                uint32_t pa[4];
                pa[0] = f2tf32(odd ? v01 : v00);
                pa[1] = f2tf32(odd ? v11 : v10);
                pa[2] = f2tf32(odd ? v21 : v20);
                pa[3] = f2tf32(odd ? v31 : v30);
#pragma unroll
                for (int j2 = 0; j2 < 8; j2++) {
                    uint32_t b0 = vs[(kk * 8 + qq) * VSTR + j2 * 8 + r];
                    uint32_t b1 = vs[(kk * 8 + qq + 4) * VSTR + j2 * 8 + r];
                    mma_tf32(o[j2], pa, b0, b1);
                }
            }
        }
        __syncthreads();
    }

    // ---- epilogue: normalize, convert to tf32 bits, store ----
    const float inv0 = 1.f / l0;
    const float inv1 = 1.f / l1;
    uint32_t* Ob = O + ((size_t)b * SEQ) * DMODEL + h * DHEAD;
    const int row0 = q0 + wm + r;
#pragma unroll
    for (int j2 = 0; j2 < 8; j2++) {
        int col = j2 * 8 + 2 * qq;
        *(uint2*)&Ob[(size_t)row0 * DMODEL + col] =
            make_uint2(f2tf32(o[j2][0] * inv0), f2tf32(o[j2][1] * inv0));
        *(uint2*)&Ob[(size_t)(row0 + 8) * DMODEL + col] =
            make_uint2(f2tf32(o[j2][2] * inv1), f2tf32(o[j2][3] * inv1));
    }
}

// ---------------------------------------------------------------------------
// Launch
// ---------------------------------------------------------------------------
extern "C" void kernel_launch(void* const* d_in, const int* in_sizes, int n_in,
                              void* d_out, int out_size)
{
    const float* x  = (const float*)d_in[0];
    const float* Wq = (const float*)d_in[1];
    const float* Wk = (const float*)d_in[2];
    const float* Wv = (const float*)d_in[3];
    const float* Wo = (const float*)d_in[4];
    float* out = (float*)d_out;

    uint32_t *q_ptr, *k_ptr, *v_ptr, *at_ptr, *xt_ptr;
    cudaGetSymbolAddress((void**)&q_ptr,  g_q);
    cudaGetSymbolAddress((void**)&k_ptr,  g_k);
    cudaGetSymbolAddress((void**)&v_ptr,  g_v);
    cudaGetSymbolAddress((void**)&at_ptr, g_at);
    cudaGetSymbolAddress((void**)&xt_ptr, g_xt);

    static int attr_set = 0;
    if (!attr_set) {
        cudaFuncSetAttribute(gemm_qkv_kernel,
                             cudaFuncAttributeMaxDynamicSharedMemorySize,
                             GEMM_SMEM_BYTES);
        cudaFuncSetAttribute(gemm_out_kernel,
                             cudaFuncAttributeMaxDynamicSharedMemorySize,
                             GEMM_SMEM_BYTES);
        cudaFuncSetAttribute(flash_mma_kernel,
                             cudaFuncAttributeMaxDynamicSharedMemorySize,
                             FLASH_SMEM);
        attr_set = 1;
    }

    // 1. pre-convert x and weights to tf32 bits
    conv_tf32_kernel<<<(MTOT * DMODEL) / (256 * 4), 256>>>(x, xt_ptr);
    conv_w_kernel<<<dim3(WELEM / (256 * 4), 1, 4), 256>>>(Wq, Wk, Wv, Wo);

    // 2. fused Q/K/V projections (outputs tf32 bits; Q pre-scaled)
    gemm_qkv_kernel<<<dim3(DMODEL / 128, MTOT / 128, 3), 256, GEMM_SMEM_BYTES>>>();

    // 3. flash attention (tf32 in, tf32 out)
    dim3 agrid(SEQ / 128, BATCH * NHEAD);   // (16, 64)
    flash_mma_kernel<<<agrid, 256, FLASH_SMEM>>>(q_ptr, k_ptr, v_ptr, at_ptr);

    // 4. output projection
    gemm_out_kernel<<<dim3(DMODEL / 128, MTOT / 128), 256, GEMM_SMEM_BYTES>>>(out);
}

// round 15
// speedup vs baseline: 4.1533x; 1.0602x over previous
#include <cuda_runtime.h>
#include <math.h>
#include <stdint.h>

// Problem constants
#define BATCH 4
#define SEQ   2048
#define DMODEL 1024
#define NHEAD 16
#define DHEAD 64
#define MTOT  (BATCH * SEQ)
#define WELEM (DMODEL * DMODEL)
// attention scale folded with log2(e): softmax computed in log2 domain
#define QSCALE (0.125f * 1.4426950408889634f)

// ---------------------------------------------------------------------------
// Scratch (device globals). q/k/v/attn hold tf32 BIT PATTERNS (uint32).
// ---------------------------------------------------------------------------
__device__ uint32_t g_q[(size_t)MTOT * DMODEL];
__device__ uint32_t g_k[(size_t)MTOT * DMODEL];
__device__ uint32_t g_v[(size_t)MTOT * DMODEL];
__device__ uint32_t g_at[(size_t)MTOT * DMODEL];
__device__ uint32_t g_xt[(size_t)MTOT * DMODEL];
__device__ uint32_t g_wt[(size_t)4 * WELEM];

__device__ __forceinline__ uint32_t f2tf32(float x) {
    uint32_t u;
    asm("cvt.rna.tf32.f32 %0, %1;" : "=r"(u) : "f"(x));
    return u;
}

__device__ __forceinline__ float ex2(float x) {
    float y;
    asm("ex2.approx.ftz.f32 %0, %1;" : "=f"(y) : "f"(x));
    return y;
}

__device__ __forceinline__ void mma_tf32(float c[4], const uint32_t a[4],
                                         uint32_t b0, uint32_t b1) {
    asm volatile(
        "mma.sync.aligned.m16n8k8.row.col.f32.tf32.tf32.f32 "
        "{%0,%1,%2,%3}, {%4,%5,%6,%7}, {%8,%9}, {%0,%1,%2,%3};\n"
        : "+f"(c[0]), "+f"(c[1]), "+f"(c[2]), "+f"(c[3])
        : "r"(a[0]), "r"(a[1]), "r"(a[2]), "r"(a[3]), "r"(b0), "r"(b1));
}

// ---------------------------------------------------------------------------
// fp32 -> tf32-bits conversion kernels
// ---------------------------------------------------------------------------
__global__ __launch_bounds__(256)
void conv_tf32_kernel(const float* __restrict__ in, uint32_t* __restrict__ out)
{
    size_t i = ((size_t)blockIdx.x * 256 + threadIdx.x) * 4;
    float4 v = *(const float4*)&in[i];
    *(uint4*)&out[i] = make_uint4(f2tf32(v.x), f2tf32(v.y), f2tf32(v.z), f2tf32(v.w));
}

__global__ __launch_bounds__(256)
void conv_w_kernel(const float* __restrict__ w0, const float* __restrict__ w1,
                   const float* __restrict__ w2, const float* __restrict__ w3)
{
    const float* src = (blockIdx.z == 0) ? w0 : (blockIdx.z == 1) ? w1
                     : (blockIdx.z == 2) ? w2 : w3;
    size_t i = ((size_t)blockIdx.x * 256 + threadIdx.x) * 4;
    float4 v = *(const float4*)&src[i];
    *(uint4*)&g_wt[(size_t)blockIdx.z * WELEM + i] =
        make_uint4(f2tf32(v.x), f2tf32(v.y), f2tf32(v.z), f2tf32(v.w));
}

// ---------------------------------------------------------------------------
// TF32 GEMM on tf32-bit inputs:  C = A @ W^T
// BLOCK TILE 128x256, warp tile 64x64 (8 warps in 2m x 4n), K-tile 32,
// 3-stage cp.async pipeline. Row stride 36 words (144B): 16B-aligned for
// cp.async; 36 = 4 mod 32 keeps fragment LDS conflict-free.
// Per k8 sub-step each warp issues 32 LDS.32 for 32 MMAs (was 24:16).
// ---------------------------------------------------------------------------
#define GKT   32
#define GSROW 36
#define GA_U32 (128 * GSROW)                        // 4608 words / stage
#define GB_U32 (256 * GSROW)                        // 9216 words / stage
#define GEMM_SMEM_BYTES (3 * (GA_U32 + GB_U32) * 4) // 165888 B

template<bool CVT>
__device__ __forceinline__
void gemm_body(uint32_t* smem, const uint32_t* __restrict__ A,
               const uint32_t* __restrict__ W, float* __restrict__ C,
               uint32_t* __restrict__ Ct, float oscale,
               int M, int N, int K, int bm, int bn)
{
    uint32_t* As = smem;                    // [3][128*GSROW]
    uint32_t* Bs = smem + 3 * GA_U32;       // [3][256*GSROW]

    const int tid = threadIdx.x;
    const int lane = tid & 31;
    const int warp = tid >> 5;
    const int wm = (warp >> 2) * 64;        // 0 or 64
    const int wn = (warp & 3) * 64;         // 0,64,128,192
    const int r = lane >> 2;
    const int qq = lane & 3;

    const uint32_t s_as = (uint32_t)__cvta_generic_to_shared(As);
    const uint32_t s_bs = (uint32_t)__cvta_generic_to_shared(Bs);

    float c[4][8][4];
#pragma unroll
    for (int i = 0; i < 4; i++)
#pragma unroll
        for (int j = 0; j < 8; j++)
#pragma unroll
            for (int x = 0; x < 4; x++) c[i][j][x] = 0.f;

    const int NT = K / GKT;                 // 32

    auto cp_tile = [&](int kt, int buf) {
        const int k0 = kt * GKT;
        const uint32_t abase = s_as + (uint32_t)(buf * GA_U32) * 4u;
        const uint32_t bbase = s_bs + (uint32_t)(buf * GB_U32) * 4u;
#pragma unroll
        for (int l = 0; l < 4; l++) {           // A: 128 rows x 8 float4
            int idx = tid + l * 256;
            int rr = idx >> 3;
            int c4 = (idx & 7) * 4;
            uint32_t da = abase + (uint32_t)(rr * GSROW + c4) * 4u;
            const uint32_t* ga = &A[(size_t)(bm + rr) * K + k0 + c4];
            asm volatile("cp.async.ca.shared.global [%0], [%1], 16;\n"
                         :: "r"(da), "l"(ga));
        }
#pragma unroll
        for (int l = 0; l < 8; l++) {           // B: 256 rows x 8 float4
            int idx = tid + l * 256;
            int rr = idx >> 3;
            int c4 = (idx & 7) * 4;
            uint32_t db = bbase + (uint32_t)(rr * GSROW + c4) * 4u;
            const uint32_t* gb = &W[(size_t)(bn + rr) * K + k0 + c4];
            asm volatile("cp.async.ca.shared.global [%0], [%1], 16;\n"
                         :: "r"(db), "l"(gb));
        }
        asm volatile("cp.async.commit_group;\n" ::: "memory");
    };

    cp_tile(0, 0);
    cp_tile(1, 1);

    for (int kt = 0; kt < NT; kt++) {
        if (kt + 1 < NT)
            asm volatile("cp.async.wait_group 1;\n" ::: "memory");
        else
            asm volatile("cp.async.wait_group 0;\n" ::: "memory");
        __syncthreads();
        if (kt + 2 < NT) {
            int b2 = kt + 2;
            cp_tile(b2, b2 % 3);
        }

        const uint32_t* as = As + (kt % 3) * GA_U32;
        const uint32_t* bs = Bs + (kt % 3) * GB_U32;

#pragma unroll
        for (int s = 0; s < 4; s++) {
            const int kb = s * 8 + qq;
            uint32_t a[4][4], b[8][2];
#pragma unroll
            for (int i = 0; i < 4; i++) {
                const uint32_t* p = as + (wm + i * 16 + r) * GSROW + kb;
                a[i][0] = p[0];
                a[i][2] = p[4];
                const uint32_t* p8 = p + 8 * GSROW;
                a[i][1] = p8[0];
                a[i][3] = p8[4];
            }
#pragma unroll
            for (int j = 0; j < 8; j++) {
                const uint32_t* p = bs + (wn + j * 8 + r) * GSROW + kb;
                b[j][0] = p[0];
                b[j][1] = p[4];
            }
#pragma unroll
            for (int i = 0; i < 4; i++)
#pragma unroll
                for (int j = 0; j < 8; j++)
                    mma_tf32(c[i][j], a[i], b[j][0], b[j][1]);
        }
    }
    __syncthreads();

#pragma unroll
    for (int i = 0; i < 4; i++) {
#pragma unroll
        for (int j = 0; j < 8; j++) {
            int row = bm + wm + i * 16 + r;
            int col = bn + wn + j * 8 + qq * 2;
            if (CVT) {
                *(uint2*)&Ct[(size_t)row * N + col] =
                    make_uint2(f2tf32(c[i][j][0] * oscale), f2tf32(c[i][j][1] * oscale));
                *(uint2*)&Ct[(size_t)(row + 8) * N + col] =
                    make_uint2(f2tf32(c[i][j][2] * oscale), f2tf32(c[i][j][3] * oscale));
            } else {
                *(float2*)&C[(size_t)row * N + col] =
                    make_float2(c[i][j][0], c[i][j][1]);
                *(float2*)&C[(size_t)(row + 8) * N + col] =
                    make_float2(c[i][j][2], c[i][j][3]);
            }
        }
    }
}

// Fused Q/K/V projection. Q pre-scaled by QSCALE (attention scale * log2e).
__global__ __launch_bounds__(256, 1)
void gemm_qkv_kernel()
{
    extern __shared__ uint32_t smem[];
    const int z = blockIdx.z;
    uint32_t* Ct = (z == 0) ? g_q : (z == 1) ? g_k : g_v;
    float oscale = (z == 0) ? QSCALE : 1.0f;
    gemm_body<true>(smem, g_xt, g_wt + (size_t)z * WELEM, nullptr, Ct, oscale,
                    MTOT, DMODEL, DMODEL, blockIdx.y * 128, blockIdx.x * 256);
}

__global__ __launch_bounds__(256, 1)
void gemm_out_kernel(float* __restrict__ out)
{
    extern __shared__ uint32_t smem[];
    gemm_body<false>(smem, g_at, g_wt + (size_t)3 * WELEM, out, nullptr, 1.0f,
                     MTOT, DMODEL, DMODEL, blockIdx.y * 128, blockIdx.x * 256);
}

// ---------------------------------------------------------------------------
// Tensor-core causal flash attention (unchanged from round 10 / best kernel).
// 256 threads = 8 warps, Q tile 128, KV tile 64, 3-stage cp.async pipeline,
// softmax in log2 domain, all data tf32 bits.
// ---------------------------------------------------------------------------
#define KSTR 68
#define VSTR 72
#define FLASH_SMEM ((3 * 64 * KSTR + 3 * 64 * VSTR) * 4)   // 107520 B

__global__ __launch_bounds__(256, 2)
void flash_mma_kernel(const uint32_t* __restrict__ Q, const uint32_t* __restrict__ K,
                      const uint32_t* __restrict__ V, uint32_t* __restrict__ O)
{
    extern __shared__ uint32_t sm[];
    uint32_t* KsB = sm;
    uint32_t* VsB = sm + 3 * 64 * KSTR;

    const int bh = blockIdx.y;
    const int b = bh >> 4;
    const int h = bh & 15;
    const int qb = gridDim.x - 1 - blockIdx.x;
    const int q0 = qb * 128;
    const int tid = threadIdx.x;
    const int lane = tid & 31;
    const int warp = tid >> 5;
    const int wm = warp * 16;
    const int r = lane >> 2;
    const int qq = lane & 3;

    const uint32_t* Qb = Q + ((size_t)b * SEQ) * DMODEL + h * DHEAD;
    const uint32_t* Kb = K + ((size_t)b * SEQ) * DMODEL + h * DHEAD;
    const uint32_t* Vb = V + ((size_t)b * SEQ) * DMODEL + h * DHEAD;

#pragma unroll
    for (int i = 0; i < 8; i++) {
        int idx = tid + i * 256;
        int rr = idx >> 4;
        int cc = (idx & 15) * 4;
        *(uint4*)&KsB[rr * KSTR + cc] = *(const uint4*)&Qb[(size_t)(q0 + rr) * DMODEL + cc];
    }
    __syncthreads();

    uint32_t qf[8][4];
#pragma unroll
    for (int kk = 0; kk < 8; kk++) {
        qf[kk][0] = KsB[(wm + r) * KSTR + kk * 8 + qq];
        qf[kk][1] = KsB[(wm + r + 8) * KSTR + kk * 8 + qq];
        qf[kk][2] = KsB[(wm + r) * KSTR + kk * 8 + qq + 4];
        qf[kk][3] = KsB[(wm + r + 8) * KSTR + kk * 8 + qq + 4];
    }
    __syncthreads();

    float o[8][4];
#pragma unroll
    for (int j = 0; j < 8; j++)
#pragma unroll
        for (int x = 0; x < 4; x++) o[j][x] = 0.f;
    float m0 = -INFINITY, m1 = -INFINITY;
    float l0 = 0.f, l1 = 0.f;

    const int base = lane & 28;
    const int sl0 = base + (qq >> 1);
    const int sl1 = sl0 + 2;
    const bool odd = (qq & 1);

    const int nt = 2 * qb + 2;
    const uint32_t s_k = (uint32_t)__cvta_generic_to_shared(KsB);
    const uint32_t s_v = (uint32_t)__cvta_generic_to_shared(VsB);

    auto cp_tile = [&](int t, int buf) {
        const int k0 = t * 64;
        const uint32_t kb = s_k + (uint32_t)(buf * 64 * KSTR) * 4u;
        const uint32_t vb = s_v + (uint32_t)(buf * 64 * VSTR) * 4u;
#pragma unroll
        for (int l = 0; l < 4; l++) {
            int idx = tid + l * 256;
            int rr = idx >> 4;
            int cc = (idx & 15) * 4;
            uint32_t dk = kb + (uint32_t)(rr * KSTR + cc) * 4u;
            const uint32_t* gk = &Kb[(size_t)(k0 + rr) * DMODEL + cc];
            asm volatile("cp.async.ca.shared.global [%0], [%1], 16;\n"
                         :: "r"(dk), "l"(gk));
            uint32_t dv = vb + (uint32_t)(rr * VSTR + cc) * 4u;
            const uint32_t* gv = &Vb[(size_t)(k0 + rr) * DMODEL + cc];
            asm volatile("cp.async.ca.shared.global [%0], [%1], 16;\n"
                         :: "r"(dv), "l"(gv));
        }
        asm volatile("cp.async.commit_group;\n" ::: "memory");
    };

    cp_tile(0, 0);
    if (nt > 1) cp_tile(1, 1);

    for (int t = 0; t < nt; t++) {
        if (t + 1 < nt)
            asm volatile("cp.async.wait_group 1;\n" ::: "memory");
        else
            asm volatile("cp.async.wait_group 0;\n" ::: "memory");
        __syncthreads();
        if (t + 2 < nt) cp_tile(t + 2, (t + 2) % 3);

        const uint32_t* ks = KsB + (t % 3) * 64 * KSTR;
        const uint32_t* vs = VsB + (t % 3) * 64 * VSTR;
        const int k0 = t * 64;

        if (k0 <= q0 + wm + 15) {
            float cf[8][4];
#pragma unroll
            for (int j = 0; j < 8; j++) {
#pragma unroll
                for (int x = 0; x < 4; x++) cf[j][x] = 0.f;
#pragma unroll
                for (int kk = 0; kk < 8; kk++) {
                    uint32_t b0 = ks[(j * 8 + r) * KSTR + kk * 8 + qq];
                    uint32_t b1 = ks[(j * 8 + r) * KSTR + kk * 8 + qq + 4];
                    mma_tf32(cf[j], qf[kk], b0, b1);
                }
            }

            if (t >= nt - 2) {
                const int row0 = q0 + wm + r;
                const int row1 = row0 + 8;
#pragma unroll
                for (int j = 0; j < 8; j++) {
                    int kc = k0 + j * 8 + 2 * qq;
                    if (kc > row0)     cf[j][0] = -INFINITY;
                    if (kc + 1 > row0) cf[j][1] = -INFINITY;
                    if (kc > row1)     cf[j][2] = -INFINITY;
                    if (kc + 1 > row1) cf[j][3] = -INFINITY;
                }
            }

            float t0 = -INFINITY, t1 = -INFINITY;
#pragma unroll
            for (int j = 0; j < 8; j++) {
                t0 = fmaxf(t0, fmaxf(cf[j][0], cf[j][1]));
                t1 = fmaxf(t1, fmaxf(cf[j][2], cf[j][3]));
            }
            t0 = fmaxf(t0, __shfl_xor_sync(0xffffffffu, t0, 1));
            t0 = fmaxf(t0, __shfl_xor_sync(0xffffffffu, t0, 2));
            t1 = fmaxf(t1, __shfl_xor_sync(0xffffffffu, t1, 1));
            t1 = fmaxf(t1, __shfl_xor_sync(0xffffffffu, t1, 2));

            float nm0 = fmaxf(m0, t0);
            float nm1 = fmaxf(m1, t1);
            float alpha0 = ex2(m0 - nm0);
            float alpha1 = ex2(m1 - nm1);
            m0 = nm0; m1 = nm1;

            float rs0 = 0.f, rs1 = 0.f;
#pragma unroll
            for (int j = 0; j < 8; j++) {
                cf[j][0] = ex2(cf[j][0] - m0); rs0 += cf[j][0];
                cf[j][1] = ex2(cf[j][1] - m0); rs0 += cf[j][1];
                cf[j][2] = ex2(cf[j][2] - m1); rs1 += cf[j][2];
                cf[j][3] = ex2(cf[j][3] - m1); rs1 += cf[j][3];
            }
            rs0 += __shfl_xor_sync(0xffffffffu, rs0, 1);
            rs0 += __shfl_xor_sync(0xffffffffu, rs0, 2);
            rs1 += __shfl_xor_sync(0xffffffffu, rs1, 1);
            rs1 += __shfl_xor_sync(0xffffffffu, rs1, 2);
            l0 = l0 * alpha0 + rs0;
            l1 = l1 * alpha1 + rs1;

#pragma unroll
            for (int j = 0; j < 8; j++) {
                o[j][0] *= alpha0; o[j][1] *= alpha0;
                o[j][2] *= alpha1; o[j][3] *= alpha1;
            }

#pragma unroll
            for (int kk = 0; kk < 8; kk++) {
                float v00 = __shfl_sync(0xffffffffu, cf[kk][0], sl0);
                float v01 = __shfl_sync(0xffffffffu, cf[kk][1], sl0);
                float v20 = __shfl_sync(0xffffffffu, cf[kk][0], sl1);
                float v21 = __shfl_sync(0xffffffffu, cf[kk][1], sl1);
                float v10 = __shfl_sync(0xffffffffu, cf[kk][2], sl0);
                float v11 = __shfl_sync(0xffffffffu, cf[kk][3], sl0);
                float v30 = __shfl_sync(0xffffffffu, cf[kk][2], sl1);
                float v31 = __shfl_sync(0xffffffffu, cf[kk][3], sl1);
                uint32_t pa[4];
                pa[0] = f2tf32(odd ? v01 : v00);
                pa[1] = f2tf32(odd ? v11 : v10);
                pa[2] = f2tf32(odd ? v21 : v20);
                pa[3] = f2tf32(odd ? v31 : v30);
#pragma unroll
                for (int j2 = 0; j2 < 8; j2++) {
                    uint32_t b0 = vs[(kk * 8 + qq) * VSTR + j2 * 8 + r];
                    uint32_t b1 = vs[(kk * 8 + qq + 4) * VSTR + j2 * 8 + r];
                    mma_tf32(o[j2], pa, b0, b1);
                }
            }
        }
        __syncthreads();
    }

    const float inv0 = 1.f / l0;
    const float inv1 = 1.f / l1;
    uint32_t* Ob = O + ((size_t)b * SEQ) * DMODEL + h * DHEAD;
    const int row0 = q0 + wm + r;
#pragma unroll
    for (int j2 = 0; j2 < 8; j2++) {
        int col = j2 * 8 + 2 * qq;
        *(uint2*)&Ob[(size_t)row0 * DMODEL + col] =
            make_uint2(f2tf32(o[j2][0] * inv0), f2tf32(o[j2][1] * inv0));
        *(uint2*)&Ob[(size_t)(row0 + 8) * DMODEL + col] =
            make_uint2(f2tf32(o[j2][2] * inv1), f2tf32(o[j2][3] * inv1));
    }
}

// ---------------------------------------------------------------------------
// Launch
// ---------------------------------------------------------------------------
extern "C" void kernel_launch(void* const* d_in, const int* in_sizes, int n_in,
                              void* d_out, int out_size)
{
    const float* x  = (const float*)d_in[0];
    const float* Wq = (const float*)d_in[1];
    const float* Wk = (const float*)d_in[2];
    const float* Wv = (const float*)d_in[3];
    const float* Wo = (const float*)d_in[4];
    float* out = (float*)d_out;

    uint32_t *q_ptr, *k_ptr, *v_ptr, *at_ptr, *xt_ptr;
    cudaGetSymbolAddress((void**)&q_ptr,  g_q);
    cudaGetSymbolAddress((void**)&k_ptr,  g_k);
    cudaGetSymbolAddress((void**)&v_ptr,  g_v);
    cudaGetSymbolAddress((void**)&at_ptr, g_at);
    cudaGetSymbolAddress((void**)&xt_ptr, g_xt);

    static int attr_set = 0;
    if (!attr_set) {
        cudaFuncSetAttribute(gemm_qkv_kernel,
                             cudaFuncAttributeMaxDynamicSharedMemorySize,
                             GEMM_SMEM_BYTES);
        cudaFuncSetAttribute(gemm_out_kernel,
                             cudaFuncAttributeMaxDynamicSharedMemorySize,
                             GEMM_SMEM_BYTES);
        cudaFuncSetAttribute(flash_mma_kernel,
                             cudaFuncAttributeMaxDynamicSharedMemorySize,
                             FLASH_SMEM);
        attr_set = 1;
    }

    // 1. pre-convert x and weights to tf32 bits
    conv_tf32_kernel<<<(MTOT * DMODEL) / (256 * 4), 256>>>(x, xt_ptr);
    conv_w_kernel<<<dim3(WELEM / (256 * 4), 1, 4), 256>>>(Wq, Wk, Wv, Wo);

    // 2. fused Q/K/V projections (outputs tf32 bits; Q pre-scaled)
    gemm_qkv_kernel<<<dim3(DMODEL / 256, MTOT / 128, 3), 256, GEMM_SMEM_BYTES>>>();

    // 3. flash attention (tf32 in, tf32 out)
    dim3 agrid(SEQ / 128, BATCH * NHEAD);   // (16, 64)
    flash_mma_kernel<<<agrid, 256, FLASH_SMEM>>>(q_ptr, k_ptr, v_ptr, at_ptr);

    // 4. output projection
    gemm_out_kernel<<<dim3(DMODEL / 256, MTOT / 128), 256, GEMM_SMEM_BYTES>>>(out);
}